// round 11
// baseline (speedup 1.0000x reference)
#include <cuda_runtime.h>
#include <cuda_bf16.h>
#include <math.h>
#include <stdint.h>

#define Bn 64
#define Sn 128
#define Hn 512
#define En 300
#define Vn 50257
#define H2n 1024
#define H3n 1536
#define XDIM 1324
#define CDIM 1836
#define CDIMP 1840
#define NEGV -1e10f
#define KT 16

#define PRED_OFF 0
#define HN_OFF   ((size_t)Bn * Vn)
#define A_OFF    (HN_OFF + (size_t)Bn * Hn)

// ---------------- scratch ----------------
__device__ __align__(16) float g_scorep[Bn * 8 * Sn];
__device__ __align__(16) float g_xin[Bn * XDIM];
__device__ __align__(16) float g_p_hid[KT * Bn * Hn];
__device__ __align__(16) float g_p_gx[KT * Bn * H3n];
__device__ __align__(16) float g_p_gh[KT * Bn * H3n];
__device__ __align__(16) __nv_bfloat16 g_enc_hi[(size_t)Sn * Bn * H2n];
__device__ __align__(16) __nv_bfloat16 g_enc_lo[(size_t)Sn * Bn * H2n];
__device__ __align__(16) __nv_bfloat16 g_wa_hi[Hn * H2n];
__device__ __align__(16) __nv_bfloat16 g_wa_lo[Hn * H2n];
__device__ __align__(16) __nv_bfloat16 g_xcat_hi[Bn * CDIMP];
__device__ __align__(16) __nv_bfloat16 g_xcat_lo[Bn * CDIMP];

// ---------------- helpers ----------------
__device__ __forceinline__ uint32_t smem_u32(const void* p) {
    uint32_t a;
    asm("{ .reg .u64 t; cvta.to.shared.u64 t, %1; cvt.u32.u64 %0, t; }" : "=r"(a) : "l"(p));
    return a;
}
__device__ __forceinline__ float2 lds2(uint32_t a) {
    float2 v;
    asm volatile("ld.shared.v2.f32 {%0,%1}, [%2];" : "=f"(v.x), "=f"(v.y) : "r"(a));
    return v;
}
__device__ __forceinline__ void cpa_cg(uint32_t dst, const void* src, int bytes) {
    asm volatile("cp.async.cg.shared.global [%0], [%1], 16, %2;"
                 :: "r"(dst), "l"(src), "r"(bytes) : "memory");
}
#define CPA_COMMIT() asm volatile("cp.async.commit_group;" ::: "memory")
#define CPA_WAIT1()  asm volatile("cp.async.wait_group 1;" ::: "memory")

__device__ __forceinline__ void ldmx4(uint32_t* r, uint32_t addr) {
    asm volatile("ldmatrix.sync.aligned.m8n8.x4.shared.b16 {%0,%1,%2,%3}, [%4];"
                 : "=r"(r[0]), "=r"(r[1]), "=r"(r[2]), "=r"(r[3]) : "r"(addr));
}
__device__ __forceinline__ void mma16816(float* c, const uint32_t* a, const uint32_t* b) {
    asm volatile("mma.sync.aligned.m16n8k16.row.col.f32.bf16.bf16.f32 "
                 "{%0,%1,%2,%3}, {%4,%5,%6,%7}, {%8,%9}, {%0,%1,%2,%3};"
                 : "+f"(c[0]), "+f"(c[1]), "+f"(c[2]), "+f"(c[3])
                 : "r"(a[0]), "r"(a[1]), "r"(a[2]), "r"(a[3]), "r"(b[0]), "r"(b[1]));
}
__device__ __forceinline__ void split2t(float x, float y, uint32_t& hiw, uint32_t& low) {
    uint32_t xb = __float_as_uint(x), yb = __float_as_uint(y);
    uint32_t hx = xb & 0xFFFF0000u, hy = yb & 0xFFFF0000u;
    hiw = (hx >> 16) | hy;
    float lx = x - __uint_as_float(hx);
    float ly = y - __uint_as_float(hy);
    asm("cvt.rn.bf16x2.f32 %0, %1, %2;" : "=r"(low) : "f"(ly), "f"(lx));
}
__device__ __forceinline__ uint32_t swaddr(int row, int k) {
    return (uint32_t)(row * 128 + ((((k >> 2) ^ (row & 7)) << 4)) + (k & 3) * 4);
}
__device__ __forceinline__ void split_store(float val, int idx) {
    uint32_t xb = __float_as_uint(val) & 0xFFFF0000u;
    unsigned short ht = (unsigned short)(xb >> 16);
    g_xcat_hi[idx] = *reinterpret_cast<__nv_bfloat16*>(&ht);
    g_xcat_lo[idx] = __float2bfloat16_rn(val - __uint_as_float(xb));
}

// ---------------- split-K partial GEMM body (float4 loads) ----------------
__device__ __forceinline__ void gemm_part_body(
        const float* __restrict__ A, int astride, int K,
        const float* __restrict__ W, int wstride,
        float* __restrict__ outp, int ostride, int j0, int ky) {
    __shared__ float As[32][65];
    __shared__ float Ws[32][33];
    const int ksl = (((K + KT - 1) / KT) + 31) & ~31;
    const int kb = ky * ksl;
    const int ke = (K < kb + ksl) ? K : (kb + ksl);
    float* op = outp + (size_t)ky * Bn * ostride;
    const int tid = threadIdx.x;
    const int tx = tid & 7, ty = tid >> 3;
    float acc[2][4];
    #pragma unroll
    for (int i = 0; i < 2; i++)
        #pragma unroll
        for (int j = 0; j < 4; j++) acc[i][j] = 0.f;

    for (int k0 = kb; k0 < ke; k0 += 32) {
        // A: 64 rows x 32 k = 512 float4
        #pragma unroll
        for (int it = 0; it < 2; it++) {
            int idx = tid + it * 256;
            int row = idx >> 3, k4 = idx & 7;
            float4 v = make_float4(0.f, 0.f, 0.f, 0.f);
            if (k0 + k4 * 4 < ke)
                v = *(const float4*)(A + (size_t)row * astride + k0 + k4 * 4);
            As[k4 * 4 + 0][row] = v.x;
            As[k4 * 4 + 1][row] = v.y;
            As[k4 * 4 + 2][row] = v.z;
            As[k4 * 4 + 3][row] = v.w;
        }
        // W: 32 rows x 32 k = 256 float4
        {
            int row = tid >> 3, k4 = tid & 7;
            float4 v = make_float4(0.f, 0.f, 0.f, 0.f);
            if (k0 + k4 * 4 < ke)
                v = *(const float4*)(W + (size_t)(j0 + row) * wstride + k0 + k4 * 4);
            Ws[k4 * 4 + 0][row] = v.x;
            Ws[k4 * 4 + 1][row] = v.y;
            Ws[k4 * 4 + 2][row] = v.z;
            Ws[k4 * 4 + 3][row] = v.w;
        }
        __syncthreads();
        #pragma unroll
        for (int kk = 0; kk < 32; kk++) {
            float a0 = As[kk][ty * 2], a1 = As[kk][ty * 2 + 1];
            float w[4];
            #pragma unroll
            for (int j = 0; j < 4; j++) w[j] = Ws[kk][tx * 4 + j];
            #pragma unroll
            for (int j = 0; j < 4; j++) {
                acc[0][j] += a0 * w[j];
                acc[1][j] += a1 * w[j];
            }
        }
        __syncthreads();
    }
    #pragma unroll
    for (int i = 0; i < 2; i++) {
        int b = ty * 2 + i;
        #pragma unroll
        for (int j = 0; j < 4; j++)
            op[(size_t)b * ostride + j0 + tx * 4 + j] = acc[i][j];
    }
}

// ---------------- 1) prep mega-kernel ----------------
#define NB_SE 8192
#define NB_WA 512
#define NB_HID (16 * KT)
#define NB_GH  (48 * KT)
#define NB_PREP (NB_SE + NB_WA + NB_HID + NB_GH)

__global__ __launch_bounds__(256)
void k_prep(const float* __restrict__ enc, const float* __restrict__ Wa,
            const float* __restrict__ hidden, const float* __restrict__ Whh) {
    const int bid = blockIdx.x;
    const int tid = threadIdx.x;
    if (bid < NB_SE) {
        size_t i4 = (size_t)bid * 256 + tid;
        float4 v = ((const float4*)enc)[i4];
        uint32_t h01, l01, h23, l23;
        split2t(v.x, v.y, h01, l01);
        split2t(v.z, v.w, h23, l23);
        ((uint32_t*)g_enc_hi)[i4 * 2]     = h01;
        ((uint32_t*)g_enc_hi)[i4 * 2 + 1] = h23;
        ((uint32_t*)g_enc_lo)[i4 * 2]     = l01;
        ((uint32_t*)g_enc_lo)[i4 * 2 + 1] = l23;
    } else if (bid < NB_SE + NB_WA) {
        int i4 = (bid - NB_SE) * 256 + tid;
        int h = i4 >> 8, k4 = i4 & 255;
        const float4 v = *(const float4*)(Wa + (size_t)h * H3n + Hn + k4 * 4);
        uint32_t h01, l01, h23, l23;
        split2t(v.x, v.y, h01, l01);
        split2t(v.z, v.w, h23, l23);
        int d = h * 512 + k4 * 2;
        ((uint32_t*)g_wa_hi)[d]     = h01;
        ((uint32_t*)g_wa_hi)[d + 1] = h23;
        ((uint32_t*)g_wa_lo)[d]     = l01;
        ((uint32_t*)g_wa_lo)[d + 1] = l23;
    } else if (bid < NB_SE + NB_WA + NB_HID) {
        int q = bid - NB_SE - NB_WA;
        gemm_part_body(hidden, Hn, Hn, Wa, H3n, g_p_hid, Hn,
                       (q & 15) * 32, q >> 4);
    } else {
        int q = bid - NB_SE - NB_WA - NB_HID;
        gemm_part_body(hidden, Hn, Hn, Whh, Hn, g_p_gh, H3n,
                       (q % 48) * 32, q / 48);
    }
}

// ---------------- 2) energy GEMM: 2-stage, occ 3 ----------------
#define NCHE 32
#define STAGE_E 30720
#define SMEM_E  (2 * STAGE_E)

__device__ __forceinline__ void pf_energy(int c, int st, uint32_t sbase,
                                          int b, int h0, int tid) {
    if (c >= NCHE) return;
    int k0 = c * 32;
    uint32_t ab = sbase + st * STAGE_E;
    #pragma unroll
    for (int pl = 0; pl < 2; pl++) {
        const __nv_bfloat16* srcA = pl ? g_enc_lo : g_enc_hi;
        #pragma unroll
        for (int it = 0; it < 2; it++) {
            int idx = tid + it * 256;
            int row = idx >> 2, ch = idx & 3;
            cpa_cg(ab + pl * 10240 + row * 80 + ch * 16,
                   srcA + ((size_t)(row * Bn + b)) * H2n + k0 + ch * 8, 16);
        }
        const __nv_bfloat16* srcB = pl ? g_wa_lo : g_wa_hi;
        {
            int row = tid >> 2, ch = tid & 3;
            cpa_cg(ab + 20480 + pl * 5120 + row * 80 + ch * 16,
                   srcB + (size_t)(h0 + row) * H2n + k0 + ch * 8, 16);
        }
    }
}

__global__ __launch_bounds__(256, 3)
void k_energy_mma(const float* __restrict__ vw, const float* __restrict__ ba) {
    extern __shared__ __align__(16) char dsm[];
    const uint32_t sbase = smem_u32(dsm);
    __shared__ float s_hid[64];
    __shared__ float s_vw[64];
    __shared__ float s_red[128][2];

    const int tid = threadIdx.x;
    const int lane = tid & 31, wid = tid >> 5;
    const int wm = wid >> 1, wn = wid & 1;
    const int gq = lane >> 2, tq = lane & 3;
    const int hc = blockIdx.x, b = blockIdx.y;
    const int h0 = hc * 64;

    if (tid < 64) {
        float v = ba[h0 + tid];
        #pragma unroll
        for (int cc = 0; cc < KT; cc++)
            v += g_p_hid[((size_t)cc * Bn + b) * Hn + h0 + tid];
        s_hid[tid] = v;
        s_vw[tid]  = vw[h0 + tid];
    }

    const int a_row = lane & 15;
    const int a_col8 = (lane >> 4) * 8;
    const int g = lane >> 3;
    const int b_row = ((g >> 1) * 8) + (lane & 7);
    const int b_col8 = (g & 1) * 8;

    float acc[2][4][4];
    #pragma unroll
    for (int i = 0; i < 2; i++)
        #pragma unroll
        for (int j = 0; j < 4; j++)
            #pragma unroll
            for (int q = 0; q < 4; q++) acc[i][j][q] = 0.f;

    pf_energy(0, 0, sbase, b, h0, tid);
    CPA_COMMIT();

    for (int c = 0; c < NCHE; c++) {
        pf_energy(c + 1, (c + 1) & 1, sbase, b, h0, tid);
        CPA_COMMIT();
        CPA_WAIT1();
        __syncthreads();
        const uint32_t ab = sbase + (c & 1) * STAGE_E;
        #pragma unroll
        for (int s = 0; s < 2; s++) {
            uint32_t ah[2][4], al[2][4];
            #pragma unroll
            for (int i = 0; i < 2; i++) {
                uint32_t off = (uint32_t)((wm * 32 + i * 16 + a_row) * 80
                                          + (s * 16 + a_col8) * 2);
                ldmx4(ah[i], ab + off);
                ldmx4(al[i], ab + 10240 + off);
            }
            uint32_t bh2[2][4], bl2[2][4];
            #pragma unroll
            for (int j2 = 0; j2 < 2; j2++) {
                uint32_t off = (uint32_t)((wn * 32 + j2 * 16 + b_row) * 80
                                          + (s * 16 + b_col8) * 2);
                ldmx4(bh2[j2], ab + 20480 + off);
                ldmx4(bl2[j2], ab + 25600 + off);
            }
            #pragma unroll
            for (int i = 0; i < 2; i++)
                #pragma unroll
                for (int j = 0; j < 4; j++) {
                    const uint32_t* Bh = &bh2[j >> 1][(j & 1) * 2];
                    const uint32_t* Bl = &bl2[j >> 1][(j & 1) * 2];
                    mma16816(acc[i][j], ah[i], Bh);
                    mma16816(acc[i][j], ah[i], Bl);
                    mma16816(acc[i][j], al[i], Bh);
                }
        }
        __syncthreads();
    }

    #pragma unroll
    for (int i = 0; i < 2; i++) {
        float p1 = 0.f, p2 = 0.f;
        #pragma unroll
        for (int j = 0; j < 4; j++) {
            int hl = wn * 32 + j * 8 + tq * 2;
            float v0 = s_vw[hl], v1 = s_vw[hl + 1];
            float hp0 = s_hid[hl], hp1 = s_hid[hl + 1];
            p1 += v0 * tanhf(acc[i][j][0] + hp0) + v1 * tanhf(acc[i][j][1] + hp1);
            p2 += v0 * tanhf(acc[i][j][2] + hp0) + v1 * tanhf(acc[i][j][3] + hp1);
        }
        p1 += __shfl_xor_sync(0xffffffffu, p1, 1);
        p1 += __shfl_xor_sync(0xffffffffu, p1, 2);
        p2 += __shfl_xor_sync(0xffffffffu, p2, 1);
        p2 += __shfl_xor_sync(0xffffffffu, p2, 2);
        if (tq == 0) {
            int s1 = wm * 32 + i * 16 + gq;
            s_red[s1][wn] = p1;
            s_red[s1 + 8][wn] = p2;
        }
    }
    __syncthreads();
    if (tid < 128)
        g_scorep[(b * 8 + hc) * Sn + tid] = s_red[tid][0] + s_red[tid][1];
}

// ---------------- 3) fused emb + softmax + weighted + xin + xcat ----------------
__global__ __launch_bounds__(256)
void k_attn_ctx(const int* __restrict__ ids, const float* __restrict__ table,
                const int* __restrict__ mask, const float* __restrict__ enc,
                float* __restrict__ out_a) {
    const int b = blockIdx.x;
    const int tid = threadIdx.x;
    __shared__ float red[128];
    __shared__ float a_s[Sn];

    float v = 0.f;
    if (tid < 128) {
        #pragma unroll
        for (int c = 0; c < 8; c++) v += g_scorep[(b * 8 + c) * Sn + tid];
        if (mask[b * Sn + tid] == 0) v = NEGV;
        red[tid] = v;
    }
    __syncthreads();
    #pragma unroll
    for (int off = 64; off > 0; off >>= 1) {
        if (tid < off) red[tid] = fmaxf(red[tid], red[tid + off]);
        __syncthreads();
    }
    float m = red[0];
    __syncthreads();
    float e = 0.f;
    if (tid < 128) { e = expf(v - m); red[tid] = e; }
    __syncthreads();
    #pragma unroll
    for (int off = 64; off > 0; off >>= 1) {
        if (tid < off) red[tid] += red[tid + off];
        __syncthreads();
    }
    if (tid < 128) {
        float a = e / red[0];
        a_s[tid] = a;
        out_a[A_OFF + b * Sn + tid] = a;
    }
    __syncthreads();

    const int e0 = tid * 4;
    float4 acc = make_float4(0.f, 0.f, 0.f, 0.f);
    #pragma unroll 4
    for (int s = 0; s < Sn; s++) {
        float a = a_s[s];
        float4 ev = *(const float4*)(enc + ((size_t)(s * Bn + b)) * H2n + e0);
        acc.x += a * ev.x; acc.y += a * ev.y; acc.z += a * ev.z; acc.w += a * ev.w;
    }
    *(float4*)(g_xin + (size_t)b * XDIM + En + e0) = acc;
    int cb = b * CDIMP + Hn + e0;
    split_store(acc.x, cb);
    split_store(acc.y, cb + 1);
    split_store(acc.z, cb + 2);
    split_store(acc.w, cb + 3);

    const int id = ids[b];
    for (int idx = tid; idx < En; idx += 256) {
        float val = table[(size_t)id * En + idx];
        g_xin[(size_t)b * XDIM + idx] = val;
        split_store(val, b * CDIMP + Hn + H2n + idx);
    }
    if (tid < CDIMP - CDIM) {
        g_xcat_hi[b * CDIMP + CDIM + tid] = __float2bfloat16_rn(0.f);
        g_xcat_lo[b * CDIMP + CDIM + tid] = __float2bfloat16_rn(0.f);
    }
}

// ---------------- 4) gx partial GEMM ----------------
__global__ __launch_bounds__(256)
void k_gemm_gx(const float* __restrict__ Wih) {
    gemm_part_body(g_xin, XDIM, XDIM, Wih, XDIM, g_p_gx, H3n,
                   blockIdx.x * 32, blockIdx.y);
}

// ---------------- 5) gates + h_new + xcat(h_new) ----------------
__global__ void k_gru(const float* __restrict__ hidden,
                      const float* __restrict__ bih, const float* __restrict__ bhh,
                      float* __restrict__ out) {
    int idx = blockIdx.x * blockDim.x + threadIdx.x;
    if (idx >= Bn * Hn) return;
    int b = idx / Hn, c = idx - b * Hn;
    float gx0 = bih[c], gx1 = bih[Hn + c], gx2 = bih[2 * Hn + c];
    float gh0 = bhh[c], gh1 = bhh[Hn + c], gh2 = bhh[2 * Hn + c];
    #pragma unroll
    for (int cc = 0; cc < KT; cc++) {
        size_t base = ((size_t)cc * Bn + b) * H3n;
        gx0 += g_p_gx[base + c];
        gx1 += g_p_gx[base + Hn + c];
        gx2 += g_p_gx[base + 2 * Hn + c];
        gh0 += g_p_gh[base + c];
        gh1 += g_p_gh[base + Hn + c];
        gh2 += g_p_gh[base + 2 * Hn + c];
    }
    float r = 1.f / (1.f + expf(-(gx0 + gh0)));
    float z = 1.f / (1.f + expf(-(gx1 + gh1)));
    float n = tanhf(gx2 + r * gh2);
    float val = (1.f - z) * n + z * hidden[(size_t)b * Hn + c];
    out[HN_OFF + b * Hn + c] = val;
    split_store(val, b * CDIMP + c);
}

// ---------------- 6) output GEMM: 2-stage, occ 3 ----------------
#define NCHO 58
#define STAGE_O 26624
#define SMEM_O  (2 * STAGE_O)

__device__ __forceinline__ void pf_out(int c, int st, uint32_t sbase,
                                       const float* Wout, int v0, int tid) {
    if (c >= NCHO) return;
    int k0 = c * 32;
    uint32_t wb = sbase + st * STAGE_O;
    #pragma unroll
    for (int it = 0; it < 4; it++) {
        int m = tid + it * 256;
        int row = m >> 3, kc = m & 7;
        int vr = v0 + row; if (vr >= Vn) vr = Vn - 1;
        int gk = k0 + kc * 4;
        int rem = CDIM - gk;
        int bytes = rem >= 4 ? 16 : (rem > 0 ? rem * 4 : 0);
        int gko = rem > 0 ? gk : 0;
        cpa_cg(wb + row * 128 + (((kc ^ (row & 7)) << 4)),
               Wout + (size_t)vr * CDIM + gko, bytes);
    }
    #pragma unroll
    for (int pl = 0; pl < 2; pl++) {
        const __nv_bfloat16* src = pl ? g_xcat_lo : g_xcat_hi;
        int row = tid >> 2, ch = tid & 3;
        int gk = k0 + ch * 8;
        int rem = CDIMP - gk;
        int bytes = rem >= 8 ? 16 : (rem > 0 ? rem * 2 : 0);
        int gko = rem > 0 ? gk : 0;
        cpa_cg(wb + 16384 + pl * 5120 + row * 80 + ch * 16,
               src + (size_t)row * CDIMP + gko, bytes);
    }
}

__global__ __launch_bounds__(256, 3)
void k_out_mma(const float* __restrict__ Wout, const float* __restrict__ bout,
               float* __restrict__ pred) {
    extern __shared__ __align__(16) char dsm[];
    const uint32_t sbase = smem_u32(dsm);
    const int tid = threadIdx.x;
    const int lane = tid & 31, wid = tid >> 5;
    const int wm = wid >> 1, wn = wid & 1;
    const int gq = lane >> 2, tq = lane & 3;
    const int v0 = blockIdx.x * 128;
    const int g = lane >> 3;
    const int b_row = ((g >> 1) * 8) + (lane & 7);
    const int b_col8 = (g & 1) * 8;

    float acc[2][4][4];
    #pragma unroll
    for (int i = 0; i < 2; i++)
        #pragma unroll
        for (int j = 0; j < 4; j++)
            #pragma unroll
            for (int q = 0; q < 4; q++) acc[i][j][q] = 0.f;

    pf_out(0, 0, sbase, Wout, v0, tid);
    CPA_COMMIT();

    for (int c = 0; c < NCHO; c++) {
        pf_out(c + 1, (c + 1) & 1, sbase, Wout, v0, tid);
        CPA_COMMIT();
        CPA_WAIT1();
        __syncthreads();
        const uint32_t wb = sbase + (c & 1) * STAGE_O;
        #pragma unroll
        for (int s = 0; s < 2; s++) {
            const int kk = s * 16 + tq * 2;
            uint32_t ah[2][4], al[2][4];
            #pragma unroll
            for (int i = 0; i < 2; i++) {
                int r = wm * 32 + i * 16 + gq;
                float2 x0 = lds2(wb + swaddr(r, kk));
                float2 x1 = lds2(wb + swaddr(r + 8, kk));
                float2 x2 = lds2(wb + swaddr(r, kk + 8));
                float2 x3 = lds2(wb + swaddr(r + 8, kk + 8));
                split2t(x0.x, x0.y, ah[i][0], al[i][0]);
                split2t(x1.x, x1.y, ah[i][1], al[i][1]);
                split2t(x2.x, x2.y, ah[i][2], al[i][2]);
                split2t(x3.x, x3.y, ah[i][3], al[i][3]);
            }
            uint32_t bh2[2][4], bl2[2][4];
            #pragma unroll
            for (int j2 = 0; j2 < 2; j2++) {
                uint32_t off = (uint32_t)((wn * 32 + j2 * 16 + b_row) * 80
                                          + (s * 16 + b_col8) * 2);
                ldmx4(bh2[j2], wb + 16384 + off);
                ldmx4(bl2[j2], wb + 21504 + off);
            }
            #pragma unroll
            for (int i = 0; i < 2; i++)
                #pragma unroll
                for (int j = 0; j < 4; j++) {
                    const uint32_t* Bh = &bh2[j >> 1][(j & 1) * 2];
                    const uint32_t* Bl = &bl2[j >> 1][(j & 1) * 2];
                    mma16816(acc[i][j], ah[i], Bh);
                    mma16816(acc[i][j], ah[i], Bl);
                    mma16816(acc[i][j], al[i], Bh);
                }
        }
        __syncthreads();
    }

    #pragma unroll
    for (int i = 0; i < 2; i++) {
        int v1 = v0 + wm * 32 + i * 16 + gq;
        int v2 = v1 + 8;
        float bo1 = (v1 < Vn) ? bout[v1] : 0.f;
        float bo2 = (v2 < Vn) ? bout[v2] : 0.f;
        #pragma unroll
        for (int j = 0; j < 4; j++) {
            int bb = wn * 32 + j * 8 + tq * 2;
            if (v1 < Vn) {
                pred[(size_t)bb * Vn + v1]       = acc[i][j][0] + bo1;
                pred[(size_t)(bb + 1) * Vn + v1] = acc[i][j][1] + bo1;
            }
            if (v2 < Vn) {
                pred[(size_t)bb * Vn + v2]       = acc[i][j][2] + bo2;
                pred[(size_t)(bb + 1) * Vn + v2] = acc[i][j][3] + bo2;
            }
        }
    }
}

// ---------------- launch ----------------
extern "C" void kernel_launch(void* const* d_in, const int* in_sizes, int n_in,
                              void* d_out, int out_size) {
    const int*   ids    = (const int*)  d_in[0];
    const float* hidden = (const float*)d_in[1];
    const float* enc    = (const float*)d_in[2];
    const int*   mask   = (const int*)  d_in[3];
    const float* table  = (const float*)d_in[4];
    const float* Wa     = (const float*)d_in[5];
    const float* ba     = (const float*)d_in[6];
    const float* vw     = (const float*)d_in[7];
    const float* Wih    = (const float*)d_in[8];
    const float* Whh    = (const float*)d_in[9];
    const float* bih    = (const float*)d_in[10];
    const float* bhh    = (const float*)d_in[11];
    const float* Wout   = (const float*)d_in[12];
    const float* bout   = (const float*)d_in[13];
    float* out = (float*)d_out;

    static int attr_done = 0;
    if (!attr_done) {
        cudaFuncSetAttribute(k_energy_mma, cudaFuncAttributeMaxDynamicSharedMemorySize, SMEM_E);
        cudaFuncSetAttribute(k_out_mma,    cudaFuncAttributeMaxDynamicSharedMemorySize, SMEM_O);
        attr_done = 1;
    }

    k_prep<<<NB_PREP, 256>>>(enc, Wa, hidden, Whh);
    k_energy_mma<<<dim3(8, Bn), 256, SMEM_E>>>(vw, ba);
    k_attn_ctx<<<Bn, 256>>>(ids, table, mask, enc, out);
    k_gemm_gx<<<dim3(48, KT), 256>>>(Wih);
    k_gru<<<(Bn * Hn + 255) / 256, 256>>>(hidden, bih, bhh, out);
    k_out_mma<<<(Vn + 127) / 128, 256, SMEM_O>>>(Wout, bout, out + PRED_OFF);
}

// round 12
// speedup vs baseline: 1.1130x; 1.1130x over previous
#include <cuda_runtime.h>
#include <cuda_bf16.h>
#include <math.h>
#include <stdint.h>

#define Bn 64
#define Sn 128
#define Hn 512
#define En 300
#define Vn 50257
#define H2n 1024
#define H3n 1536
#define XDIM 1324
#define CDIM 1836
#define CDIMP 1840
#define NEGV -1e10f
#define KT 16

#define PRED_OFF 0
#define HN_OFF   ((size_t)Bn * Vn)
#define A_OFF    (HN_OFF + (size_t)Bn * Hn)

// ---------------- scratch ----------------
__device__ __align__(16) float g_scorep[Bn * 8 * Sn];
__device__ __align__(16) float g_xin[Bn * XDIM];
__device__ __align__(16) float g_p_hid[KT * Bn * Hn];
__device__ __align__(16) float g_p_gx[KT * Bn * H3n];
__device__ __align__(16) float g_p_gh[KT * Bn * H3n];
__device__ __align__(16) __nv_bfloat16 g_enc_hi[(size_t)Sn * Bn * H2n];
__device__ __align__(16) __nv_bfloat16 g_enc_lo[(size_t)Sn * Bn * H2n];
__device__ __align__(16) __nv_bfloat16 g_wa_hi[Hn * H2n];
__device__ __align__(16) __nv_bfloat16 g_wa_lo[Hn * H2n];
__device__ __align__(16) __nv_bfloat16 g_xcat_hi[Bn * CDIMP];
__device__ __align__(16) __nv_bfloat16 g_xcat_lo[Bn * CDIMP];

// ---------------- helpers ----------------
__device__ __forceinline__ uint32_t smem_u32(const void* p) {
    uint32_t a;
    asm("{ .reg .u64 t; cvta.to.shared.u64 t, %1; cvt.u32.u64 %0, t; }" : "=r"(a) : "l"(p));
    return a;
}
__device__ __forceinline__ float2 lds2(uint32_t a) {
    float2 v;
    asm volatile("ld.shared.v2.f32 {%0,%1}, [%2];" : "=f"(v.x), "=f"(v.y) : "r"(a));
    return v;
}
__device__ __forceinline__ void cpa_cg(uint32_t dst, const void* src, int bytes) {
    asm volatile("cp.async.cg.shared.global [%0], [%1], 16, %2;"
                 :: "r"(dst), "l"(src), "r"(bytes) : "memory");
}
#define CPA_COMMIT() asm volatile("cp.async.commit_group;" ::: "memory")
#define CPA_WAIT1()  asm volatile("cp.async.wait_group 1;" ::: "memory")
#define CPA_WAIT2()  asm volatile("cp.async.wait_group 2;" ::: "memory")

__device__ __forceinline__ void ldmx4(uint32_t* r, uint32_t addr) {
    asm volatile("ldmatrix.sync.aligned.m8n8.x4.shared.b16 {%0,%1,%2,%3}, [%4];"
                 : "=r"(r[0]), "=r"(r[1]), "=r"(r[2]), "=r"(r[3]) : "r"(addr));
}
__device__ __forceinline__ void mma16816(float* c, const uint32_t* a, const uint32_t* b) {
    asm volatile("mma.sync.aligned.m16n8k16.row.col.f32.bf16.bf16.f32 "
                 "{%0,%1,%2,%3}, {%4,%5,%6,%7}, {%8,%9}, {%0,%1,%2,%3};"
                 : "+f"(c[0]), "+f"(c[1]), "+f"(c[2]), "+f"(c[3])
                 : "r"(a[0]), "r"(a[1]), "r"(a[2]), "r"(a[3]), "r"(b[0]), "r"(b[1]));
}
__device__ __forceinline__ void split2t(float x, float y, uint32_t& hiw, uint32_t& low) {
    uint32_t xb = __float_as_uint(x), yb = __float_as_uint(y);
    uint32_t hx = xb & 0xFFFF0000u, hy = yb & 0xFFFF0000u;
    hiw = (hx >> 16) | hy;
    float lx = x - __uint_as_float(hx);
    float ly = y - __uint_as_float(hy);
    asm("cvt.rn.bf16x2.f32 %0, %1, %2;" : "=r"(low) : "f"(ly), "f"(lx));
}
__device__ __forceinline__ uint32_t swaddr(int row, int k) {
    return (uint32_t)(row * 128 + ((((k >> 2) ^ (row & 7)) << 4)) + (k & 3) * 4);
}
__device__ __forceinline__ void split_store(float val, int idx) {
    uint32_t xb = __float_as_uint(val) & 0xFFFF0000u;
    unsigned short ht = (unsigned short)(xb >> 16);
    g_xcat_hi[idx] = *reinterpret_cast<__nv_bfloat16*>(&ht);
    g_xcat_lo[idx] = __float2bfloat16_rn(val - __uint_as_float(xb));
}

// ---------------- split-K partial GEMM body: 4b x 4j per thread, float4 LDS ----------------
// tile: b=64, j=64, k=32. 256 threads: tx(16)->4j, ty(16)->4b.
__device__ __forceinline__ void gemm_part_body(
        const float* __restrict__ A, int astride, int K,
        const float* __restrict__ W, int wstride,
        float* __restrict__ outp, int ostride, int j0, int ky) {
    __shared__ __align__(16) float As[32][68];
    __shared__ __align__(16) float Ws[32][68];
    const int ksl = (((K + KT - 1) / KT) + 31) & ~31;
    const int kb = ky * ksl;
    const int ke = (K < kb + ksl) ? K : (kb + ksl);
    float* op = outp + (size_t)ky * Bn * ostride;
    const int tid = threadIdx.x;
    const int tx = tid & 15, ty = tid >> 4;
    float acc[4][4];
    #pragma unroll
    for (int i = 0; i < 4; i++)
        #pragma unroll
        for (int j = 0; j < 4; j++) acc[i][j] = 0.f;

    for (int k0 = kb; k0 < ke; k0 += 32) {
        // A: 64 rows x 32 k = 512 float4 slots
        #pragma unroll
        for (int it = 0; it < 2; it++) {
            int idx = tid + it * 256;
            int row = idx >> 3, k4 = idx & 7;
            float4 v = make_float4(0.f, 0.f, 0.f, 0.f);
            if (k0 + k4 * 4 < ke)
                v = *(const float4*)(A + (size_t)row * astride + k0 + k4 * 4);
            As[k4 * 4 + 0][row] = v.x;
            As[k4 * 4 + 1][row] = v.y;
            As[k4 * 4 + 2][row] = v.z;
            As[k4 * 4 + 3][row] = v.w;
        }
        // W: 64 rows x 32 k = 512 float4 slots
        #pragma unroll
        for (int it = 0; it < 2; it++) {
            int idx = tid + it * 256;
            int row = idx >> 3, k4 = idx & 7;
            float4 v = make_float4(0.f, 0.f, 0.f, 0.f);
            if (k0 + k4 * 4 < ke)
                v = *(const float4*)(W + (size_t)(j0 + row) * wstride + k0 + k4 * 4);
            Ws[k4 * 4 + 0][row] = v.x;
            Ws[k4 * 4 + 1][row] = v.y;
            Ws[k4 * 4 + 2][row] = v.z;
            Ws[k4 * 4 + 3][row] = v.w;
        }
        __syncthreads();
        #pragma unroll
        for (int kk = 0; kk < 32; kk++) {
            float4 a = *(const float4*)&As[kk][ty * 4];
            float4 w = *(const float4*)&Ws[kk][tx * 4];
            float av[4] = {a.x, a.y, a.z, a.w};
            float wv[4] = {w.x, w.y, w.z, w.w};
            #pragma unroll
            for (int i = 0; i < 4; i++)
                #pragma unroll
                for (int j = 0; j < 4; j++)
                    acc[i][j] += av[i] * wv[j];
        }
        __syncthreads();
    }
    #pragma unroll
    for (int i = 0; i < 4; i++) {
        int b = ty * 4 + i;
        #pragma unroll
        for (int j = 0; j < 4; j++)
            op[(size_t)b * ostride + j0 + tx * 4 + j] = acc[i][j];
    }
}

// ---------------- 1) prep mega-kernel ----------------
#define NB_SE 8192
#define NB_WA 512
#define NB_HID (8 * KT)     // 8 j-tiles(64) x KT
#define NB_GH  (24 * KT)    // 24 j-tiles(64) x KT
#define NB_PREP (NB_SE + NB_WA + NB_HID + NB_GH)

__global__ __launch_bounds__(256)
void k_prep(const float* __restrict__ enc, const float* __restrict__ Wa,
            const float* __restrict__ hidden, const float* __restrict__ Whh) {
    const int bid = blockIdx.x;
    const int tid = threadIdx.x;
    if (bid < NB_SE) {
        size_t i4 = (size_t)bid * 256 + tid;
        float4 v = ((const float4*)enc)[i4];
        uint32_t h01, l01, h23, l23;
        split2t(v.x, v.y, h01, l01);
        split2t(v.z, v.w, h23, l23);
        ((uint32_t*)g_enc_hi)[i4 * 2]     = h01;
        ((uint32_t*)g_enc_hi)[i4 * 2 + 1] = h23;
        ((uint32_t*)g_enc_lo)[i4 * 2]     = l01;
        ((uint32_t*)g_enc_lo)[i4 * 2 + 1] = l23;
    } else if (bid < NB_SE + NB_WA) {
        int i4 = (bid - NB_SE) * 256 + tid;
        int h = i4 >> 8, k4 = i4 & 255;
        const float4 v = *(const float4*)(Wa + (size_t)h * H3n + Hn + k4 * 4);
        uint32_t h01, l01, h23, l23;
        split2t(v.x, v.y, h01, l01);
        split2t(v.z, v.w, h23, l23);
        int d = h * 512 + k4 * 2;
        ((uint32_t*)g_wa_hi)[d]     = h01;
        ((uint32_t*)g_wa_hi)[d + 1] = h23;
        ((uint32_t*)g_wa_lo)[d]     = l01;
        ((uint32_t*)g_wa_lo)[d + 1] = l23;
    } else if (bid < NB_SE + NB_WA + NB_HID) {
        int q = bid - NB_SE - NB_WA;
        gemm_part_body(hidden, Hn, Hn, Wa, H3n, g_p_hid, Hn,
                       (q & 7) * 64, q >> 3);
    } else {
        int q = bid - NB_SE - NB_WA - NB_HID;
        gemm_part_body(hidden, Hn, Hn, Whh, Hn, g_p_gh, H3n,
                       (q % 24) * 64, q / 24);
    }
}

// ---------------- 2) energy GEMM: ldmatrix+HMMA, 3-stage (R10 config) ----------------
#define NCHE 32
#define STAGE_E 30720
#define SMEM_E  (3 * STAGE_E)

__device__ __forceinline__ void pf_energy(int c, int st, uint32_t sbase,
                                          int b, int h0, int tid) {
    if (c >= NCHE) return;
    int k0 = c * 32;
    uint32_t ab = sbase + st * STAGE_E;
    #pragma unroll
    for (int pl = 0; pl < 2; pl++) {
        const __nv_bfloat16* srcA = pl ? g_enc_lo : g_enc_hi;
        #pragma unroll
        for (int it = 0; it < 2; it++) {
            int idx = tid + it * 256;
            int row = idx >> 2, ch = idx & 3;
            cpa_cg(ab + pl * 10240 + row * 80 + ch * 16,
                   srcA + ((size_t)(row * Bn + b)) * H2n + k0 + ch * 8, 16);
        }
        const __nv_bfloat16* srcB = pl ? g_wa_lo : g_wa_hi;
        {
            int row = tid >> 2, ch = tid & 3;
            cpa_cg(ab + 20480 + pl * 5120 + row * 80 + ch * 16,
                   srcB + (size_t)(h0 + row) * H2n + k0 + ch * 8, 16);
        }
    }
}

__global__ __launch_bounds__(256, 2)
void k_energy_mma(const float* __restrict__ vw, const float* __restrict__ ba) {
    extern __shared__ __align__(16) char dsm[];
    const uint32_t sbase = smem_u32(dsm);
    __shared__ float s_hid[64];
    __shared__ float s_vw[64];
    __shared__ float s_red[128][2];

    const int tid = threadIdx.x;
    const int lane = tid & 31, wid = tid >> 5;
    const int wm = wid >> 1, wn = wid & 1;
    const int gq = lane >> 2, tq = lane & 3;
    const int hc = blockIdx.x, b = blockIdx.y;
    const int h0 = hc * 64;

    if (tid < 64) {
        float v = ba[h0 + tid];
        #pragma unroll
        for (int cc = 0; cc < KT; cc++)
            v += g_p_hid[((size_t)cc * Bn + b) * Hn + h0 + tid];
        s_hid[tid] = v;
        s_vw[tid]  = vw[h0 + tid];
    }

    const int a_row = lane & 15;
    const int a_col8 = (lane >> 4) * 8;
    const int g = lane >> 3;
    const int b_row = ((g >> 1) * 8) + (lane & 7);
    const int b_col8 = (g & 1) * 8;

    float acc[2][4][4];
    #pragma unroll
    for (int i = 0; i < 2; i++)
        #pragma unroll
        for (int j = 0; j < 4; j++)
            #pragma unroll
            for (int q = 0; q < 4; q++) acc[i][j][q] = 0.f;

    pf_energy(0, 0, sbase, b, h0, tid); CPA_COMMIT();
    pf_energy(1, 1, sbase, b, h0, tid); CPA_COMMIT();

    for (int c = 0; c < NCHE; c++) {
        CPA_WAIT1();
        __syncthreads();
        const int st = c % 3;
        const uint32_t ab = sbase + st * STAGE_E;
        #pragma unroll
        for (int s = 0; s < 2; s++) {
            uint32_t ah[2][4], al[2][4];
            #pragma unroll
            for (int i = 0; i < 2; i++) {
                uint32_t off = (uint32_t)((wm * 32 + i * 16 + a_row) * 80
                                          + (s * 16 + a_col8) * 2);
                ldmx4(ah[i], ab + off);
                ldmx4(al[i], ab + 10240 + off);
            }
            uint32_t bh2[2][4], bl2[2][4];
            #pragma unroll
            for (int j2 = 0; j2 < 2; j2++) {
                uint32_t off = (uint32_t)((wn * 32 + j2 * 16 + b_row) * 80
                                          + (s * 16 + b_col8) * 2);
                ldmx4(bh2[j2], ab + 20480 + off);
                ldmx4(bl2[j2], ab + 25600 + off);
            }
            #pragma unroll
            for (int i = 0; i < 2; i++)
                #pragma unroll
                for (int j = 0; j < 4; j++) {
                    const uint32_t* Bh = &bh2[j >> 1][(j & 1) * 2];
                    const uint32_t* Bl = &bl2[j >> 1][(j & 1) * 2];
                    mma16816(acc[i][j], ah[i], Bh);
                    mma16816(acc[i][j], ah[i], Bl);
                    mma16816(acc[i][j], al[i], Bh);
                }
        }
        pf_energy(c + 2, (c + 2) % 3, sbase, b, h0, tid);
        CPA_COMMIT();
    }

    #pragma unroll
    for (int i = 0; i < 2; i++) {
        float p1 = 0.f, p2 = 0.f;
        #pragma unroll
        for (int j = 0; j < 4; j++) {
            int hl = wn * 32 + j * 8 + tq * 2;
            float v0 = s_vw[hl], v1 = s_vw[hl + 1];
            float hp0 = s_hid[hl], hp1 = s_hid[hl + 1];
            p1 += v0 * tanhf(acc[i][j][0] + hp0) + v1 * tanhf(acc[i][j][1] + hp1);
            p2 += v0 * tanhf(acc[i][j][2] + hp0) + v1 * tanhf(acc[i][j][3] + hp1);
        }
        p1 += __shfl_xor_sync(0xffffffffu, p1, 1);
        p1 += __shfl_xor_sync(0xffffffffu, p1, 2);
        p2 += __shfl_xor_sync(0xffffffffu, p2, 1);
        p2 += __shfl_xor_sync(0xffffffffu, p2, 2);
        if (tq == 0) {
            int s1 = wm * 32 + i * 16 + gq;
            s_red[s1][wn] = p1;
            s_red[s1 + 8][wn] = p2;
        }
    }
    __syncthreads();
    if (tid < 128)
        g_scorep[(b * 8 + hc) * Sn + tid] = s_red[tid][0] + s_red[tid][1];
}

// ---------------- 3) fused emb + softmax + weighted + xin + xcat ----------------
__global__ __launch_bounds__(256)
void k_attn_ctx(const int* __restrict__ ids, const float* __restrict__ table,
                const int* __restrict__ mask, const float* __restrict__ enc,
                float* __restrict__ out_a) {
    const int b = blockIdx.x;
    const int tid = threadIdx.x;
    __shared__ float red[128];
    __shared__ float a_s[Sn];

    float v = 0.f;
    if (tid < 128) {
        #pragma unroll
        for (int c = 0; c < 8; c++) v += g_scorep[(b * 8 + c) * Sn + tid];
        if (mask[b * Sn + tid] == 0) v = NEGV;
        red[tid] = v;
    }
    __syncthreads();
    #pragma unroll
    for (int off = 64; off > 0; off >>= 1) {
        if (tid < off) red[tid] = fmaxf(red[tid], red[tid + off]);
        __syncthreads();
    }
    float m = red[0];
    __syncthreads();
    float e = 0.f;
    if (tid < 128) { e = expf(v - m); red[tid] = e; }
    __syncthreads();
    #pragma unroll
    for (int off = 64; off > 0; off >>= 1) {
        if (tid < off) red[tid] += red[tid + off];
        __syncthreads();
    }
    if (tid < 128) {
        float a = e / red[0];
        a_s[tid] = a;
        out_a[A_OFF + b * Sn + tid] = a;
    }
    __syncthreads();

    const int e0 = tid * 4;
    float4 acc = make_float4(0.f, 0.f, 0.f, 0.f);
    #pragma unroll 4
    for (int s = 0; s < Sn; s++) {
        float a = a_s[s];
        float4 ev = *(const float4*)(enc + ((size_t)(s * Bn + b)) * H2n + e0);
        acc.x += a * ev.x; acc.y += a * ev.y; acc.z += a * ev.z; acc.w += a * ev.w;
    }
    *(float4*)(g_xin + (size_t)b * XDIM + En + e0) = acc;
    int cb = b * CDIMP + Hn + e0;
    split_store(acc.x, cb);
    split_store(acc.y, cb + 1);
    split_store(acc.z, cb + 2);
    split_store(acc.w, cb + 3);

    const int id = ids[b];
    for (int idx = tid; idx < En; idx += 256) {
        float val = table[(size_t)id * En + idx];
        g_xin[(size_t)b * XDIM + idx] = val;
        split_store(val, b * CDIMP + Hn + H2n + idx);
    }
    if (tid < CDIMP - CDIM) {
        g_xcat_hi[b * CDIMP + CDIM + tid] = __float2bfloat16_rn(0.f);
        g_xcat_lo[b * CDIMP + CDIM + tid] = __float2bfloat16_rn(0.f);
    }
}

// ---------------- 4) gx partial GEMM ----------------
__global__ __launch_bounds__(256)
void k_gemm_gx(const float* __restrict__ Wih) {
    gemm_part_body(g_xin, XDIM, XDIM, Wih, XDIM, g_p_gx, H3n,
                   blockIdx.x * 64, blockIdx.y);
}

// ---------------- 5) gates + h_new + xcat(h_new) ----------------
__global__ void k_gru(const float* __restrict__ hidden,
                      const float* __restrict__ bih, const float* __restrict__ bhh,
                      float* __restrict__ out) {
    int idx = blockIdx.x * blockDim.x + threadIdx.x;
    if (idx >= Bn * Hn) return;
    int b = idx / Hn, c = idx - b * Hn;
    float gx0 = bih[c], gx1 = bih[Hn + c], gx2 = bih[2 * Hn + c];
    float gh0 = bhh[c], gh1 = bhh[Hn + c], gh2 = bhh[2 * Hn + c];
    #pragma unroll
    for (int cc = 0; cc < KT; cc++) {
        size_t base = ((size_t)cc * Bn + b) * H3n;
        gx0 += g_p_gx[base + c];
        gx1 += g_p_gx[base + Hn + c];
        gx2 += g_p_gx[base + 2 * Hn + c];
        gh0 += g_p_gh[base + c];
        gh1 += g_p_gh[base + Hn + c];
        gh2 += g_p_gh[base + 2 * Hn + c];
    }
    float r = 1.f / (1.f + expf(-(gx0 + gh0)));
    float z = 1.f / (1.f + expf(-(gx1 + gh1)));
    float n = tanhf(gx2 + r * gh2);
    float val = (1.f - z) * n + z * hidden[(size_t)b * Hn + c];
    out[HN_OFF + b * Hn + c] = val;
    split_store(val, b * CDIMP + c);
}

// ---------------- 6) output GEMM: 4-stage pipeline (R10 config) ----------------
#define NCHO 58
#define STAGE_O 26624
#define SMEM_O  (4 * STAGE_O)

__device__ __forceinline__ void pf_out(int c, int st, uint32_t sbase,
                                       const float* Wout, int v0, int tid) {
    if (c >= NCHO) return;
    int k0 = c * 32;
    uint32_t wb = sbase + st * STAGE_O;
    #pragma unroll
    for (int it = 0; it < 4; it++) {
        int m = tid + it * 256;
        int row = m >> 3, kc = m & 7;
        int vr = v0 + row; if (vr >= Vn) vr = Vn - 1;
        int gk = k0 + kc * 4;
        int rem = CDIM - gk;
        int bytes = rem >= 4 ? 16 : (rem > 0 ? rem * 4 : 0);
        int gko = rem > 0 ? gk : 0;
        cpa_cg(wb + row * 128 + (((kc ^ (row & 7)) << 4)),
               Wout + (size_t)vr * CDIM + gko, bytes);
    }
    #pragma unroll
    for (int pl = 0; pl < 2; pl++) {
        const __nv_bfloat16* src = pl ? g_xcat_lo : g_xcat_hi;
        int row = tid >> 2, ch = tid & 3;
        int gk = k0 + ch * 8;
        int rem = CDIMP - gk;
        int bytes = rem >= 8 ? 16 : (rem > 0 ? rem * 2 : 0);
        int gko = rem > 0 ? gk : 0;
        cpa_cg(wb + 16384 + pl * 5120 + row * 80 + ch * 16,
               src + (size_t)row * CDIMP + gko, bytes);
    }
}

__global__ __launch_bounds__(256, 2)
void k_out_mma(const float* __restrict__ Wout, const float* __restrict__ bout,
               float* __restrict__ pred) {
    extern __shared__ __align__(16) char dsm[];
    const uint32_t sbase = smem_u32(dsm);
    const int tid = threadIdx.x;
    const int lane = tid & 31, wid = tid >> 5;
    const int wm = wid >> 1, wn = wid & 1;
    const int gq = lane >> 2, tq = lane & 3;
    const int v0 = blockIdx.x * 128;
    const int g = lane >> 3;
    const int b_row = ((g >> 1) * 8) + (lane & 7);
    const int b_col8 = (g & 1) * 8;

    float acc[2][4][4];
    #pragma unroll
    for (int i = 0; i < 2; i++)
        #pragma unroll
        for (int j = 0; j < 4; j++)
            #pragma unroll
            for (int q = 0; q < 4; q++) acc[i][j][q] = 0.f;

    pf_out(0, 0, sbase, Wout, v0, tid); CPA_COMMIT();
    pf_out(1, 1, sbase, Wout, v0, tid); CPA_COMMIT();
    pf_out(2, 2, sbase, Wout, v0, tid); CPA_COMMIT();

    for (int c = 0; c < NCHO; c++) {
        CPA_WAIT2();
        __syncthreads();
        const int st = c & 3;
        const uint32_t wb = sbase + st * STAGE_O;
        #pragma unroll
        for (int s = 0; s < 2; s++) {
            const int kk = s * 16 + tq * 2;
            uint32_t ah[2][4], al[2][4];
            #pragma unroll
            for (int i = 0; i < 2; i++) {
                int r = wm * 32 + i * 16 + gq;
                float2 x0 = lds2(wb + swaddr(r, kk));
                float2 x1 = lds2(wb + swaddr(r + 8, kk));
                float2 x2 = lds2(wb + swaddr(r, kk + 8));
                float2 x3 = lds2(wb + swaddr(r + 8, kk + 8));
                split2t(x0.x, x0.y, ah[i][0], al[i][0]);
                split2t(x1.x, x1.y, ah[i][1], al[i][1]);
                split2t(x2.x, x2.y, ah[i][2], al[i][2]);
                split2t(x3.x, x3.y, ah[i][3], al[i][3]);
            }
            uint32_t bh2[2][4], bl2[2][4];
            #pragma unroll
            for (int j2 = 0; j2 < 2; j2++) {
                uint32_t off = (uint32_t)((wn * 32 + j2 * 16 + b_row) * 80
                                          + (s * 16 + b_col8) * 2);
                ldmx4(bh2[j2], wb + 16384 + off);
                ldmx4(bl2[j2], wb + 21504 + off);
            }
            #pragma unroll
            for (int i = 0; i < 2; i++)
                #pragma unroll
                for (int j = 0; j < 4; j++) {
                    const uint32_t* Bh = &bh2[j >> 1][(j & 1) * 2];
                    const uint32_t* Bl = &bl2[j >> 1][(j & 1) * 2];
                    mma16816(acc[i][j], ah[i], Bh);
                    mma16816(acc[i][j], ah[i], Bl);
                    mma16816(acc[i][j], al[i], Bh);
                }
        }
        pf_out(c + 3, (c + 3) & 3, sbase, Wout, v0, tid);
        CPA_COMMIT();
    }

    #pragma unroll
    for (int i = 0; i < 2; i++) {
        int v1 = v0 + wm * 32 + i * 16 + gq;
        int v2 = v1 + 8;
        float bo1 = (v1 < Vn) ? bout[v1] : 0.f;
        float bo2 = (v2 < Vn) ? bout[v2] : 0.f;
        #pragma unroll
        for (int j = 0; j < 4; j++) {
            int bb = wn * 32 + j * 8 + tq * 2;
            if (v1 < Vn) {
                pred[(size_t)bb * Vn + v1]       = acc[i][j][0] + bo1;
                pred[(size_t)(bb + 1) * Vn + v1] = acc[i][j][1] + bo1;
            }
            if (v2 < Vn) {
                pred[(size_t)bb * Vn + v2]       = acc[i][j][2] + bo2;
                pred[(size_t)(bb + 1) * Vn + v2] = acc[i][j][3] + bo2;
            }
        }
    }
}

// ---------------- launch ----------------
extern "C" void kernel_launch(void* const* d_in, const int* in_sizes, int n_in,
                              void* d_out, int out_size) {
    const int*   ids    = (const int*)  d_in[0];
    const float* hidden = (const float*)d_in[1];
    const float* enc    = (const float*)d_in[2];
    const int*   mask   = (const int*)  d_in[3];
    const float* table  = (const float*)d_in[4];
    const float* Wa     = (const float*)d_in[5];
    const float* ba     = (const float*)d_in[6];
    const float* vw     = (const float*)d_in[7];
    const float* Wih    = (const float*)d_in[8];
    const float* Whh    = (const float*)d_in[9];
    const float* bih    = (const float*)d_in[10];
    const float* bhh    = (const float*)d_in[11];
    const float* Wout   = (const float*)d_in[12];
    const float* bout   = (const float*)d_in[13];
    float* out = (float*)d_out;

    static int attr_done = 0;
    if (!attr_done) {
        cudaFuncSetAttribute(k_energy_mma, cudaFuncAttributeMaxDynamicSharedMemorySize, SMEM_E);
        cudaFuncSetAttribute(k_out_mma,    cudaFuncAttributeMaxDynamicSharedMemorySize, SMEM_O);
        attr_done = 1;
    }

    k_prep<<<NB_PREP, 256>>>(enc, Wa, hidden, Whh);
    k_energy_mma<<<dim3(8, Bn), 256, SMEM_E>>>(vw, ba);
    k_attn_ctx<<<Bn, 256>>>(ids, table, mask, enc, out);
    k_gemm_gx<<<dim3(24, KT), 256>>>(Wih);
    k_gru<<<(Bn * Hn + 255) / 256, 256>>>(hidden, bih, bhh, out);
    k_out_mma<<<(Vn + 127) / 128, 256, SMEM_O>>>(Wout, bout, out + PRED_OFF);
}

// round 13
// speedup vs baseline: 1.3213x; 1.1871x over previous
#include <cuda_runtime.h>
#include <cuda_fp16.h>
#include <math.h>
#include <stdint.h>

#define Bn 64
#define Sn 128
#define Hn 512
#define En 300
#define Vn 50257
#define H2n 1024
#define H3n 1536
#define XDIM 1324
#define CDIM 1836
#define CDIMP 1840
#define NEGV -1e10f
#define KT 16

#define PRED_OFF 0
#define HN_OFF   ((size_t)Bn * Vn)
#define A_OFF    (HN_OFF + (size_t)Bn * Hn)

// ---------------- scratch ----------------
__device__ __align__(16) float g_scorep[Bn * 8 * Sn];
__device__ __align__(16) float g_xin[Bn * XDIM];
__device__ __align__(16) float g_p_hid[KT * Bn * Hn];
__device__ __align__(16) float g_p_gx[KT * Bn * H3n];
__device__ __align__(16) float g_p_gh[KT * Bn * H3n];
__device__ __align__(16) __half g_enc_h[(size_t)Sn * Bn * H2n];
__device__ __align__(16) __half g_wa_hi[Hn * H2n];
__device__ __align__(16) __half g_wa_lo[Hn * H2n];
__device__ __align__(16) __half g_xcat_hi[Bn * CDIMP];
__device__ __align__(16) __half g_xcat_lo[Bn * CDIMP];

// ---------------- helpers ----------------
__device__ __forceinline__ uint32_t smem_u32(const void* p) {
    uint32_t a;
    asm("{ .reg .u64 t; cvta.to.shared.u64 t, %1; cvt.u32.u64 %0, t; }" : "=r"(a) : "l"(p));
    return a;
}
__device__ __forceinline__ float2 lds2(uint32_t a) {
    float2 v;
    asm volatile("ld.shared.v2.f32 {%0,%1}, [%2];" : "=f"(v.x), "=f"(v.y) : "r"(a));
    return v;
}
__device__ __forceinline__ void cpa_cg(uint32_t dst, const void* src, int bytes) {
    asm volatile("cp.async.cg.shared.global [%0], [%1], 16, %2;"
                 :: "r"(dst), "l"(src), "r"(bytes) : "memory");
}
#define CPA_COMMIT() asm volatile("cp.async.commit_group;" ::: "memory")
#define CPA_WAIT1()  asm volatile("cp.async.wait_group 1;" ::: "memory")
#define CPA_WAIT2()  asm volatile("cp.async.wait_group 2;" ::: "memory")

__device__ __forceinline__ void ldmx4(uint32_t* r, uint32_t addr) {
    asm volatile("ldmatrix.sync.aligned.m8n8.x4.shared.b16 {%0,%1,%2,%3}, [%4];"
                 : "=r"(r[0]), "=r"(r[1]), "=r"(r[2]), "=r"(r[3]) : "r"(addr));
}
__device__ __forceinline__ void mma16816(float* c, const uint32_t* a, const uint32_t* b) {
    asm volatile("mma.sync.aligned.m16n8k16.row.col.f32.f16.f16.f32 "
                 "{%0,%1,%2,%3}, {%4,%5,%6,%7}, {%8,%9}, {%0,%1,%2,%3};"
                 : "+f"(c[0]), "+f"(c[1]), "+f"(c[2]), "+f"(c[3])
                 : "r"(a[0]), "r"(a[1]), "r"(a[2]), "r"(a[3]), "r"(b[0]), "r"(b[1]));
}
// pack two floats into fp16x2 (lo = x, hi = y)
__device__ __forceinline__ uint32_t pack2h(float x, float y) {
    uint32_t r;
    asm("cvt.rn.f16x2.f32 %0, %1, %2;" : "=r"(r) : "f"(y), "f"(x));
    return r;
}
// fp16 hi/lo split: hiw = fp16(x,y), low = fp16 residuals
__device__ __forceinline__ void split2h(float x, float y, uint32_t& hiw, uint32_t& low) {
    hiw = pack2h(x, y);
    __half2 h = *reinterpret_cast<__half2*>(&hiw);
    float lx = x - __half2float(h.x);
    float ly = y - __half2float(h.y);
    low = pack2h(lx, ly);
}
__device__ __forceinline__ uint32_t swaddr(int row, int k) {
    return (uint32_t)(row * 128 + ((((k >> 2) ^ (row & 7)) << 4)) + (k & 3) * 4);
}
__device__ __forceinline__ void split_store(float val, int idx) {
    __half h = __float2half_rn(val);
    g_xcat_hi[idx] = h;
    g_xcat_lo[idx] = __float2half_rn(val - __half2float(h));
}

// ---------------- split-K partial GEMM body: 4b x 4j, float4 LDS ----------------
__device__ __forceinline__ void gemm_part_body(
        const float* __restrict__ A, int astride, int K,
        const float* __restrict__ W, int wstride,
        float* __restrict__ outp, int ostride, int j0, int ky) {
    __shared__ __align__(16) float As[32][68];
    __shared__ __align__(16) float Ws[32][68];
    const int ksl = (((K + KT - 1) / KT) + 31) & ~31;
    const int kb = ky * ksl;
    const int ke = (K < kb + ksl) ? K : (kb + ksl);
    float* op = outp + (size_t)ky * Bn * ostride;
    const int tid = threadIdx.x;
    const int tx = tid & 15, ty = tid >> 4;
    float acc[4][4];
    #pragma unroll
    for (int i = 0; i < 4; i++)
        #pragma unroll
        for (int j = 0; j < 4; j++) acc[i][j] = 0.f;

    for (int k0 = kb; k0 < ke; k0 += 32) {
        #pragma unroll
        for (int it = 0; it < 2; it++) {
            int idx = tid + it * 256;
            int row = idx >> 3, k4 = idx & 7;
            float4 v = make_float4(0.f, 0.f, 0.f, 0.f);
            if (k0 + k4 * 4 < ke)
                v = *(const float4*)(A + (size_t)row * astride + k0 + k4 * 4);
            As[k4 * 4 + 0][row] = v.x;
            As[k4 * 4 + 1][row] = v.y;
            As[k4 * 4 + 2][row] = v.z;
            As[k4 * 4 + 3][row] = v.w;
        }
        #pragma unroll
        for (int it = 0; it < 2; it++) {
            int idx = tid + it * 256;
            int row = idx >> 3, k4 = idx & 7;
            float4 v = make_float4(0.f, 0.f, 0.f, 0.f);
            if (k0 + k4 * 4 < ke)
                v = *(const float4*)(W + (size_t)(j0 + row) * wstride + k0 + k4 * 4);
            Ws[k4 * 4 + 0][row] = v.x;
            Ws[k4 * 4 + 1][row] = v.y;
            Ws[k4 * 4 + 2][row] = v.z;
            Ws[k4 * 4 + 3][row] = v.w;
        }
        __syncthreads();
        #pragma unroll
        for (int kk = 0; kk < 32; kk++) {
            float4 a = *(const float4*)&As[kk][ty * 4];
            float4 w = *(const float4*)&Ws[kk][tx * 4];
            float av[4] = {a.x, a.y, a.z, a.w};
            float wv[4] = {w.x, w.y, w.z, w.w};
            #pragma unroll
            for (int i = 0; i < 4; i++)
                #pragma unroll
                for (int j = 0; j < 4; j++)
                    acc[i][j] += av[i] * wv[j];
        }
        __syncthreads();
    }
    #pragma unroll
    for (int i = 0; i < 4; i++) {
        int b = ty * 4 + i;
        #pragma unroll
        for (int j = 0; j < 4; j++)
            op[(size_t)b * ostride + j0 + tx * 4 + j] = acc[i][j];
    }
}

// ---------------- 1) prep mega-kernel ----------------
#define NB_SE 8192
#define NB_WA 512
#define NB_HID (8 * KT)
#define NB_GH  (24 * KT)
#define NB_PREP (NB_SE + NB_WA + NB_HID + NB_GH)

__global__ __launch_bounds__(256)
void k_prep(const float* __restrict__ enc, const float* __restrict__ Wa,
            const float* __restrict__ hidden, const float* __restrict__ Whh) {
    const int bid = blockIdx.x;
    const int tid = threadIdx.x;
    if (bid < NB_SE) {
        size_t i4 = (size_t)bid * 256 + tid;
        float4 v = ((const float4*)enc)[i4];
        ((uint32_t*)g_enc_h)[i4 * 2]     = pack2h(v.x, v.y);
        ((uint32_t*)g_enc_h)[i4 * 2 + 1] = pack2h(v.z, v.w);
    } else if (bid < NB_SE + NB_WA) {
        int i4 = (bid - NB_SE) * 256 + tid;
        int h = i4 >> 8, k4 = i4 & 255;
        const float4 v = *(const float4*)(Wa + (size_t)h * H3n + Hn + k4 * 4);
        uint32_t h01, l01, h23, l23;
        split2h(v.x, v.y, h01, l01);
        split2h(v.z, v.w, h23, l23);
        int d = h * 512 + k4 * 2;
        ((uint32_t*)g_wa_hi)[d]     = h01;
        ((uint32_t*)g_wa_hi)[d + 1] = h23;
        ((uint32_t*)g_wa_lo)[d]     = l01;
        ((uint32_t*)g_wa_lo)[d + 1] = l23;
    } else if (bid < NB_SE + NB_WA + NB_HID) {
        int q = bid - NB_SE - NB_WA;
        gemm_part_body(hidden, Hn, Hn, Wa, H3n, g_p_hid, Hn,
                       (q & 7) * 64, q >> 3);
    } else {
        int q = bid - NB_SE - NB_WA - NB_HID;
        gemm_part_body(hidden, Hn, Hn, Whh, Hn, g_p_gh, H3n,
                       (q % 24) * 64, q / 24);
    }
}

// ---------------- 2) energy GEMM: enc_hi x (Wa_hi + Wa_lo), 3-stage ----------------
#define NCHE 32
#define STAGE_E 20480     // A 10240 | Bhi 5120 | Blo 5120
#define SMEM_E  (3 * STAGE_E)

__device__ __forceinline__ void pf_energy(int c, int st, uint32_t sbase,
                                          int b, int h0, int tid) {
    if (c >= NCHE) return;
    int k0 = c * 32;
    uint32_t ab = sbase + st * STAGE_E;
    #pragma unroll
    for (int it = 0; it < 2; it++) {
        int idx = tid + it * 256;
        int row = idx >> 2, ch = idx & 3;
        cpa_cg(ab + row * 80 + ch * 16,
               g_enc_h + ((size_t)(row * Bn + b)) * H2n + k0 + ch * 8, 16);
    }
    {
        int row = tid >> 2, ch = tid & 3;
        cpa_cg(ab + 10240 + row * 80 + ch * 16,
               g_wa_hi + (size_t)(h0 + row) * H2n + k0 + ch * 8, 16);
        cpa_cg(ab + 15360 + row * 80 + ch * 16,
               g_wa_lo + (size_t)(h0 + row) * H2n + k0 + ch * 8, 16);
    }
}

__global__ __launch_bounds__(256, 2)
void k_energy_mma(const float* __restrict__ vw, const float* __restrict__ ba) {
    extern __shared__ __align__(16) char dsm[];
    const uint32_t sbase = smem_u32(dsm);
    __shared__ float s_hid[64];
    __shared__ float s_vw[64];
    __shared__ float s_red[128][2];

    const int tid = threadIdx.x;
    const int lane = tid & 31, wid = tid >> 5;
    const int wm = wid >> 1, wn = wid & 1;
    const int gq = lane >> 2, tq = lane & 3;
    const int hc = blockIdx.x, b = blockIdx.y;
    const int h0 = hc * 64;

    if (tid < 64) {
        float v = ba[h0 + tid];
        #pragma unroll
        for (int cc = 0; cc < KT; cc++)
            v += g_p_hid[((size_t)cc * Bn + b) * Hn + h0 + tid];
        s_hid[tid] = v;
        s_vw[tid]  = vw[h0 + tid];
    }

    const int a_row = lane & 15;
    const int a_col8 = (lane >> 4) * 8;
    const int g = lane >> 3;
    const int b_row = ((g >> 1) * 8) + (lane & 7);
    const int b_col8 = (g & 1) * 8;

    float acc[2][4][4];
    #pragma unroll
    for (int i = 0; i < 2; i++)
        #pragma unroll
        for (int j = 0; j < 4; j++)
            #pragma unroll
            for (int q = 0; q < 4; q++) acc[i][j][q] = 0.f;

    pf_energy(0, 0, sbase, b, h0, tid); CPA_COMMIT();
    pf_energy(1, 1, sbase, b, h0, tid); CPA_COMMIT();

    for (int c = 0; c < NCHE; c++) {
        CPA_WAIT1();
        __syncthreads();
        const int st = c % 3;
        const uint32_t ab = sbase + st * STAGE_E;
        #pragma unroll
        for (int s = 0; s < 2; s++) {
            uint32_t ah[2][4];
            #pragma unroll
            for (int i = 0; i < 2; i++) {
                uint32_t off = (uint32_t)((wm * 32 + i * 16 + a_row) * 80
                                          + (s * 16 + a_col8) * 2);
                ldmx4(ah[i], ab + off);
            }
            uint32_t bh2[2][4], bl2[2][4];
            #pragma unroll
            for (int j2 = 0; j2 < 2; j2++) {
                uint32_t off = (uint32_t)((wn * 32 + j2 * 16 + b_row) * 80
                                          + (s * 16 + b_col8) * 2);
                ldmx4(bh2[j2], ab + 10240 + off);
                ldmx4(bl2[j2], ab + 15360 + off);
            }
            #pragma unroll
            for (int i = 0; i < 2; i++)
                #pragma unroll
                for (int j = 0; j < 4; j++) {
                    const uint32_t* Bh = &bh2[j >> 1][(j & 1) * 2];
                    const uint32_t* Bl = &bl2[j >> 1][(j & 1) * 2];
                    mma16816(acc[i][j], ah[i], Bh);
                    mma16816(acc[i][j], ah[i], Bl);
                }
        }
        pf_energy(c + 2, (c + 2) % 3, sbase, b, h0, tid);
        CPA_COMMIT();
    }

    #pragma unroll
    for (int i = 0; i < 2; i++) {
        float p1 = 0.f, p2 = 0.f;
        #pragma unroll
        for (int j = 0; j < 4; j++) {
            int hl = wn * 32 + j * 8 + tq * 2;
            float v0 = s_vw[hl], v1 = s_vw[hl + 1];
            float hp0 = s_hid[hl], hp1 = s_hid[hl + 1];
            p1 += v0 * tanhf(acc[i][j][0] + hp0) + v1 * tanhf(acc[i][j][1] + hp1);
            p2 += v0 * tanhf(acc[i][j][2] + hp0) + v1 * tanhf(acc[i][j][3] + hp1);
        }
        p1 += __shfl_xor_sync(0xffffffffu, p1, 1);
        p1 += __shfl_xor_sync(0xffffffffu, p1, 2);
        p2 += __shfl_xor_sync(0xffffffffu, p2, 1);
        p2 += __shfl_xor_sync(0xffffffffu, p2, 2);
        if (tq == 0) {
            int s1 = wm * 32 + i * 16 + gq;
            s_red[s1][wn] = p1;
            s_red[s1 + 8][wn] = p2;
        }
    }
    __syncthreads();
    if (tid < 128)
        g_scorep[(b * 8 + hc) * Sn + tid] = s_red[tid][0] + s_red[tid][1];
}

// ---------------- 3) fused emb + softmax + weighted + xin + xcat ----------------
__global__ __launch_bounds__(256)
void k_attn_ctx(const int* __restrict__ ids, const float* __restrict__ table,
                const int* __restrict__ mask, const float* __restrict__ enc,
                float* __restrict__ out_a) {
    const int b = blockIdx.x;
    const int tid = threadIdx.x;
    __shared__ float red[128];
    __shared__ float a_s[Sn];

    float v = 0.f;
    if (tid < 128) {
        #pragma unroll
        for (int c = 0; c < 8; c++) v += g_scorep[(b * 8 + c) * Sn + tid];
        if (mask[b * Sn + tid] == 0) v = NEGV;
        red[tid] = v;
    }
    __syncthreads();
    #pragma unroll
    for (int off = 64; off > 0; off >>= 1) {
        if (tid < off) red[tid] = fmaxf(red[tid], red[tid + off]);
        __syncthreads();
    }
    float m = red[0];
    __syncthreads();
    float e = 0.f;
    if (tid < 128) { e = expf(v - m); red[tid] = e; }
    __syncthreads();
    #pragma unroll
    for (int off = 64; off > 0; off >>= 1) {
        if (tid < off) red[tid] += red[tid + off];
        __syncthreads();
    }
    if (tid < 128) {
        float a = e / red[0];
        a_s[tid] = a;
        out_a[A_OFF + b * Sn + tid] = a;
    }
    __syncthreads();

    const int e0 = tid * 4;
    float4 acc = make_float4(0.f, 0.f, 0.f, 0.f);
    #pragma unroll 4
    for (int s = 0; s < Sn; s++) {
        float a = a_s[s];
        float4 ev = *(const float4*)(enc + ((size_t)(s * Bn + b)) * H2n + e0);
        acc.x += a * ev.x; acc.y += a * ev.y; acc.z += a * ev.z; acc.w += a * ev.w;
    }
    *(float4*)(g_xin + (size_t)b * XDIM + En + e0) = acc;
    int cb = b * CDIMP + Hn + e0;
    split_store(acc.x, cb);
    split_store(acc.y, cb + 1);
    split_store(acc.z, cb + 2);
    split_store(acc.w, cb + 3);

    const int id = ids[b];
    for (int idx = tid; idx < En; idx += 256) {
        float val = table[(size_t)id * En + idx];
        g_xin[(size_t)b * XDIM + idx] = val;
        split_store(val, b * CDIMP + Hn + H2n + idx);
    }
    if (tid < CDIMP - CDIM) {
        g_xcat_hi[b * CDIMP + CDIM + tid] = __float2half_rn(0.f);
        g_xcat_lo[b * CDIMP + CDIM + tid] = __float2half_rn(0.f);
    }
}

// ---------------- 4) gx partial GEMM ----------------
__global__ __launch_bounds__(256)
void k_gemm_gx(const float* __restrict__ Wih) {
    gemm_part_body(g_xin, XDIM, XDIM, Wih, XDIM, g_p_gx, H3n,
                   blockIdx.x * 64, blockIdx.y);
}

// ---------------- 5) gates + h_new + xcat(h_new) ----------------
__global__ void k_gru(const float* __restrict__ hidden,
                      const float* __restrict__ bih, const float* __restrict__ bhh,
                      float* __restrict__ out) {
    int idx = blockIdx.x * blockDim.x + threadIdx.x;
    if (idx >= Bn * Hn) return;
    int b = idx / Hn, c = idx - b * Hn;
    float gx0 = bih[c], gx1 = bih[Hn + c], gx2 = bih[2 * Hn + c];
    float gh0 = bhh[c], gh1 = bhh[Hn + c], gh2 = bhh[2 * Hn + c];
    #pragma unroll
    for (int cc = 0; cc < KT; cc++) {
        size_t base = ((size_t)cc * Bn + b) * H3n;
        gx0 += g_p_gx[base + c];
        gx1 += g_p_gx[base + Hn + c];
        gx2 += g_p_gx[base + 2 * Hn + c];
        gh0 += g_p_gh[base + c];
        gh1 += g_p_gh[base + Hn + c];
        gh2 += g_p_gh[base + 2 * Hn + c];
    }
    float r = 1.f / (1.f + expf(-(gx0 + gh0)));
    float z = 1.f / (1.f + expf(-(gx1 + gh1)));
    float n = tanhf(gx2 + r * gh2);
    float val = (1.f - z) * n + z * hidden[(size_t)b * Hn + c];
    out[HN_OFF + b * Hn + c] = val;
    split_store(val, b * CDIMP + c);
}

// ---------------- 6) output GEMM: W_h x (X_hi + X_lo), 4-stage ----------------
#define NCHO 58
#define STAGE_O 26624      // W fp32 16384 | Xhi 5120 | Xlo 5120
#define SMEM_O  (4 * STAGE_O)

__device__ __forceinline__ void pf_out(int c, int st, uint32_t sbase,
                                       const float* Wout, int v0, int tid) {
    if (c >= NCHO) return;
    int k0 = c * 32;
    uint32_t wb = sbase + st * STAGE_O;
    #pragma unroll
    for (int it = 0; it < 4; it++) {
        int m = tid + it * 256;
        int row = m >> 3, kc = m & 7;
        int vr = v0 + row; if (vr >= Vn) vr = Vn - 1;
        int gk = k0 + kc * 4;
        int rem = CDIM - gk;
        int bytes = rem >= 4 ? 16 : (rem > 0 ? rem * 4 : 0);
        int gko = rem > 0 ? gk : 0;
        cpa_cg(wb + row * 128 + (((kc ^ (row & 7)) << 4)),
               Wout + (size_t)vr * CDIM + gko, bytes);
    }
    #pragma unroll
    for (int pl = 0; pl < 2; pl++) {
        const __half* src = pl ? g_xcat_lo : g_xcat_hi;
        int row = tid >> 2, ch = tid & 3;
        int gk = k0 + ch * 8;
        int rem = CDIMP - gk;
        int bytes = rem >= 8 ? 16 : (rem > 0 ? rem * 2 : 0);
        int gko = rem > 0 ? gk : 0;
        cpa_cg(wb + 16384 + pl * 5120 + row * 80 + ch * 16,
               src + (size_t)row * CDIMP + gko, bytes);
    }
}

__global__ __launch_bounds__(256, 2)
void k_out_mma(const float* __restrict__ Wout, const float* __restrict__ bout,
               float* __restrict__ pred) {
    extern __shared__ __align__(16) char dsm[];
    const uint32_t sbase = smem_u32(dsm);
    const int tid = threadIdx.x;
    const int lane = tid & 31, wid = tid >> 5;
    const int wm = wid >> 1, wn = wid & 1;
    const int gq = lane >> 2, tq = lane & 3;
    const int v0 = blockIdx.x * 128;
    const int g = lane >> 3;
    const int b_row = ((g >> 1) * 8) + (lane & 7);
    const int b_col8 = (g & 1) * 8;

    float acc[2][4][4];
    #pragma unroll
    for (int i = 0; i < 2; i++)
        #pragma unroll
        for (int j = 0; j < 4; j++)
            #pragma unroll
            for (int q = 0; q < 4; q++) acc[i][j][q] = 0.f;

    pf_out(0, 0, sbase, Wout, v0, tid); CPA_COMMIT();
    pf_out(1, 1, sbase, Wout, v0, tid); CPA_COMMIT();
    pf_out(2, 2, sbase, Wout, v0, tid); CPA_COMMIT();

    for (int c = 0; c < NCHO; c++) {
        CPA_WAIT2();
        __syncthreads();
        const int st = c & 3;
        const uint32_t wb = sbase + st * STAGE_O;
        #pragma unroll
        for (int s = 0; s < 2; s++) {
            const int kk = s * 16 + tq * 2;
            uint32_t ah[2][4];
            #pragma unroll
            for (int i = 0; i < 2; i++) {
                int r = wm * 32 + i * 16 + gq;
                float2 x0 = lds2(wb + swaddr(r, kk));
                float2 x1 = lds2(wb + swaddr(r + 8, kk));
                float2 x2 = lds2(wb + swaddr(r, kk + 8));
                float2 x3 = lds2(wb + swaddr(r + 8, kk + 8));
                ah[i][0] = pack2h(x0.x, x0.y);
                ah[i][1] = pack2h(x1.x, x1.y);
                ah[i][2] = pack2h(x2.x, x2.y);
                ah[i][3] = pack2h(x3.x, x3.y);
            }
            uint32_t bh2[2][4], bl2[2][4];
            #pragma unroll
            for (int j2 = 0; j2 < 2; j2++) {
                uint32_t off = (uint32_t)((wn * 32 + j2 * 16 + b_row) * 80
                                          + (s * 16 + b_col8) * 2);
                ldmx4(bh2[j2], wb + 16384 + off);
                ldmx4(bl2[j2], wb + 21504 + off);
            }
            #pragma unroll
            for (int i = 0; i < 2; i++)
                #pragma unroll
                for (int j = 0; j < 4; j++) {
                    const uint32_t* Bh = &bh2[j >> 1][(j & 1) * 2];
                    const uint32_t* Bl = &bl2[j >> 1][(j & 1) * 2];
                    mma16816(acc[i][j], ah[i], Bh);
                    mma16816(acc[i][j], ah[i], Bl);
                }
        }
        pf_out(c + 3, (c + 3) & 3, sbase, Wout, v0, tid);
        CPA_COMMIT();
    }

    #pragma unroll
    for (int i = 0; i < 2; i++) {
        int v1 = v0 + wm * 32 + i * 16 + gq;
        int v2 = v1 + 8;
        float bo1 = (v1 < Vn) ? bout[v1] : 0.f;
        float bo2 = (v2 < Vn) ? bout[v2] : 0.f;
        #pragma unroll
        for (int j = 0; j < 4; j++) {
            int bb = wn * 32 + j * 8 + tq * 2;
            if (v1 < Vn) {
                pred[(size_t)bb * Vn + v1]       = acc[i][j][0] + bo1;
                pred[(size_t)(bb + 1) * Vn + v1] = acc[i][j][1] + bo1;
            }
            if (v2 < Vn) {
                pred[(size_t)bb * Vn + v2]       = acc[i][j][2] + bo2;
                pred[(size_t)(bb + 1) * Vn + v2] = acc[i][j][3] + bo2;
            }
        }
    }
}

// ---------------- launch ----------------
extern "C" void kernel_launch(void* const* d_in, const int* in_sizes, int n_in,
                              void* d_out, int out_size) {
    const int*   ids    = (const int*)  d_in[0];
    const float* hidden = (const float*)d_in[1];
    const float* enc    = (const float*)d_in[2];
    const int*   mask   = (const int*)  d_in[3];
    const float* table  = (const float*)d_in[4];
    const float* Wa     = (const float*)d_in[5];
    const float* ba     = (const float*)d_in[6];
    const float* vw     = (const float*)d_in[7];
    const float* Wih    = (const float*)d_in[8];
    const float* Whh    = (const float*)d_in[9];
    const float* bih    = (const float*)d_in[10];
    const float* bhh    = (const float*)d_in[11];
    const float* Wout   = (const float*)d_in[12];
    const float* bout   = (const float*)d_in[13];
    float* out = (float*)d_out;

    static int attr_done = 0;
    if (!attr_done) {
        cudaFuncSetAttribute(k_energy_mma, cudaFuncAttributeMaxDynamicSharedMemorySize, SMEM_E);
        cudaFuncSetAttribute(k_out_mma,    cudaFuncAttributeMaxDynamicSharedMemorySize, SMEM_O);
        attr_done = 1;
    }

    k_prep<<<NB_PREP, 256>>>(enc, Wa, hidden, Whh);
    k_energy_mma<<<dim3(8, Bn), 256, SMEM_E>>>(vw, ba);
    k_attn_ctx<<<Bn, 256>>>(ids, table, mask, enc, out);
    k_gemm_gx<<<dim3(24, KT), 256>>>(Wih);
    k_gru<<<(Bn * Hn + 255) / 256, 256>>>(hidden, bih, bhh, out);
    k_out_mma<<<(Vn + 127) / 128, 256, SMEM_O>>>(Wout, bout, out + PRED_OFF);
}

// round 14
// speedup vs baseline: 1.6015x; 1.2121x over previous
#include <cuda_runtime.h>
#include <cuda_fp16.h>
#include <math.h>
#include <stdint.h>

#define Bn 64
#define Sn 128
#define Hn 512
#define En 300
#define Vn 50257
#define H2n 1024
#define H3n 1536
#define XDIM 1324
#define CDIM 1836
#define CDIMP 1840
#define NEGV -1e10f
#define KT 16

#define PRED_OFF 0
#define HN_OFF   ((size_t)Bn * Vn)
#define A_OFF    (HN_OFF + (size_t)Bn * Hn)

// ---------------- scratch ----------------
__device__ __align__(16) float g_scorep[Bn * 8 * Sn];
__device__ __align__(16) float g_xin[Bn * XDIM];
__device__ __align__(16) float g_p_hid[KT * Bn * Hn];
__device__ __align__(16) float g_p_gx[KT * Bn * H3n];
__device__ __align__(16) float g_p_gh[KT * Bn * H3n];
__device__ __align__(16) __half g_enc_h[(size_t)Sn * Bn * H2n];
__device__ __align__(16) __half g_wa_h[Hn * H2n];
__device__ __align__(16) __half g_xcat_h[Bn * CDIMP];

// ---------------- helpers ----------------
__device__ __forceinline__ uint32_t smem_u32(const void* p) {
    uint32_t a;
    asm("{ .reg .u64 t; cvta.to.shared.u64 t, %1; cvt.u32.u64 %0, t; }" : "=r"(a) : "l"(p));
    return a;
}
__device__ __forceinline__ float2 lds2(uint32_t a) {
    float2 v;
    asm volatile("ld.shared.v2.f32 {%0,%1}, [%2];" : "=f"(v.x), "=f"(v.y) : "r"(a));
    return v;
}
__device__ __forceinline__ void cpa_cg(uint32_t dst, const void* src, int bytes) {
    asm volatile("cp.async.cg.shared.global [%0], [%1], 16, %2;"
                 :: "r"(dst), "l"(src), "r"(bytes) : "memory");
}
#define CPA_COMMIT() asm volatile("cp.async.commit_group;" ::: "memory")
#define CPA_WAIT1()  asm volatile("cp.async.wait_group 1;" ::: "memory")
#define CPA_WAIT2()  asm volatile("cp.async.wait_group 2;" ::: "memory")

__device__ __forceinline__ void ldmx4(uint32_t* r, uint32_t addr) {
    asm volatile("ldmatrix.sync.aligned.m8n8.x4.shared.b16 {%0,%1,%2,%3}, [%4];"
                 : "=r"(r[0]), "=r"(r[1]), "=r"(r[2]), "=r"(r[3]) : "r"(addr));
}
__device__ __forceinline__ void mma16816(float* c, const uint32_t* a, const uint32_t* b) {
    asm volatile("mma.sync.aligned.m16n8k16.row.col.f32.f16.f16.f32 "
                 "{%0,%1,%2,%3}, {%4,%5,%6,%7}, {%8,%9}, {%0,%1,%2,%3};"
                 : "+f"(c[0]), "+f"(c[1]), "+f"(c[2]), "+f"(c[3])
                 : "r"(a[0]), "r"(a[1]), "r"(a[2]), "r"(a[3]), "r"(b[0]), "r"(b[1]));
}
__device__ __forceinline__ uint32_t pack2h(float x, float y) {
    uint32_t r;
    asm("cvt.rn.f16x2.f32 %0, %1, %2;" : "=r"(r) : "f"(y), "f"(x));
    return r;
}
__device__ __forceinline__ uint32_t swaddr(int row, int k) {
    return (uint32_t)(row * 128 + ((((k >> 2) ^ (row & 7)) << 4)) + (k & 3) * 4);
}

// ---------------- split-K partial GEMM body: 4b x 4j, float4 LDS ----------------
__device__ __forceinline__ void gemm_part_body(
        const float* __restrict__ A, int astride, int K,
        const float* __restrict__ W, int wstride,
        float* __restrict__ outp, int ostride, int j0, int ky) {
    __shared__ __align__(16) float As[32][68];
    __shared__ __align__(16) float Ws[32][68];
    const int ksl = (((K + KT - 1) / KT) + 31) & ~31;
    const int kb = ky * ksl;
    const int ke = (K < kb + ksl) ? K : (kb + ksl);
    float* op = outp + (size_t)ky * Bn * ostride;
    const int tid = threadIdx.x;
    const int tx = tid & 15, ty = tid >> 4;
    float acc[4][4];
    #pragma unroll
    for (int i = 0; i < 4; i++)
        #pragma unroll
        for (int j = 0; j < 4; j++) acc[i][j] = 0.f;

    for (int k0 = kb; k0 < ke; k0 += 32) {
        #pragma unroll
        for (int it = 0; it < 2; it++) {
            int idx = tid + it * 256;
            int row = idx >> 3, k4 = idx & 7;
            float4 v = make_float4(0.f, 0.f, 0.f, 0.f);
            if (k0 + k4 * 4 < ke)
                v = *(const float4*)(A + (size_t)row * astride + k0 + k4 * 4);
            As[k4 * 4 + 0][row] = v.x;
            As[k4 * 4 + 1][row] = v.y;
            As[k4 * 4 + 2][row] = v.z;
            As[k4 * 4 + 3][row] = v.w;
        }
        #pragma unroll
        for (int it = 0; it < 2; it++) {
            int idx = tid + it * 256;
            int row = idx >> 3, k4 = idx & 7;
            float4 v = make_float4(0.f, 0.f, 0.f, 0.f);
            if (k0 + k4 * 4 < ke)
                v = *(const float4*)(W + (size_t)(j0 + row) * wstride + k0 + k4 * 4);
            Ws[k4 * 4 + 0][row] = v.x;
            Ws[k4 * 4 + 1][row] = v.y;
            Ws[k4 * 4 + 2][row] = v.z;
            Ws[k4 * 4 + 3][row] = v.w;
        }
        __syncthreads();
        #pragma unroll
        for (int kk = 0; kk < 32; kk++) {
            float4 a = *(const float4*)&As[kk][ty * 4];
            float4 w = *(const float4*)&Ws[kk][tx * 4];
            float av[4] = {a.x, a.y, a.z, a.w};
            float wv[4] = {w.x, w.y, w.z, w.w};
            #pragma unroll
            for (int i = 0; i < 4; i++)
                #pragma unroll
                for (int j = 0; j < 4; j++)
                    acc[i][j] += av[i] * wv[j];
        }
        __syncthreads();
    }
    #pragma unroll
    for (int i = 0; i < 4; i++) {
        int b = ty * 4 + i;
        #pragma unroll
        for (int j = 0; j < 4; j++)
            op[(size_t)b * ostride + j0 + tx * 4 + j] = acc[i][j];
    }
}

// ---------------- 1) prep mega-kernel ----------------
#define NB_SE 8192
#define NB_WA 512
#define NB_HID (8 * KT)
#define NB_GH  (24 * KT)
#define NB_PREP (NB_SE + NB_WA + NB_HID + NB_GH)

__global__ __launch_bounds__(256)
void k_prep(const float* __restrict__ enc, const float* __restrict__ Wa,
            const float* __restrict__ hidden, const float* __restrict__ Whh) {
    const int bid = blockIdx.x;
    const int tid = threadIdx.x;
    if (bid < NB_SE) {
        size_t i4 = (size_t)bid * 256 + tid;
        float4 v = ((const float4*)enc)[i4];
        ((uint32_t*)g_enc_h)[i4 * 2]     = pack2h(v.x, v.y);
        ((uint32_t*)g_enc_h)[i4 * 2 + 1] = pack2h(v.z, v.w);
    } else if (bid < NB_SE + NB_WA) {
        int i4 = (bid - NB_SE) * 256 + tid;
        int h = i4 >> 8, k4 = i4 & 255;
        const float4 v = *(const float4*)(Wa + (size_t)h * H3n + Hn + k4 * 4);
        int d = h * 512 + k4 * 2;
        ((uint32_t*)g_wa_h)[d]     = pack2h(v.x, v.y);
        ((uint32_t*)g_wa_h)[d + 1] = pack2h(v.z, v.w);
    } else if (bid < NB_SE + NB_WA + NB_HID) {
        int q = bid - NB_SE - NB_WA;
        gemm_part_body(hidden, Hn, Hn, Wa, H3n, g_p_hid, Hn,
                       (q & 7) * 64, q >> 3);
    } else {
        int q = bid - NB_SE - NB_WA - NB_HID;
        gemm_part_body(hidden, Hn, Hn, Whh, Hn, g_p_gh, H3n,
                       (q % 24) * 64, q / 24);
    }
}

// ---------------- 2) energy GEMM: enc_h x Wa_h, single MMA, 3-stage ----------------
#define NCHE 32
#define STAGE_E 15360     // A 10240 | B 5120
#define SMEM_E  (3 * STAGE_E)

__device__ __forceinline__ void pf_energy(int c, int st, uint32_t sbase,
                                          int b, int h0, int tid) {
    if (c >= NCHE) return;
    int k0 = c * 32;
    uint32_t ab = sbase + st * STAGE_E;
    #pragma unroll
    for (int it = 0; it < 2; it++) {
        int idx = tid + it * 256;
        int row = idx >> 2, ch = idx & 3;
        cpa_cg(ab + row * 80 + ch * 16,
               g_enc_h + ((size_t)(row * Bn + b)) * H2n + k0 + ch * 8, 16);
    }
    {
        int row = tid >> 2, ch = tid & 3;
        cpa_cg(ab + 10240 + row * 80 + ch * 16,
               g_wa_h + (size_t)(h0 + row) * H2n + k0 + ch * 8, 16);
    }
}

__global__ __launch_bounds__(256, 2)
void k_energy_mma(const float* __restrict__ vw, const float* __restrict__ ba) {
    extern __shared__ __align__(16) char dsm[];
    const uint32_t sbase = smem_u32(dsm);
    __shared__ float s_hid[64];
    __shared__ float s_vw[64];
    __shared__ float s_red[128][2];

    const int tid = threadIdx.x;
    const int lane = tid & 31, wid = tid >> 5;
    const int wm = wid >> 1, wn = wid & 1;
    const int gq = lane >> 2, tq = lane & 3;
    const int hc = blockIdx.x, b = blockIdx.y;
    const int h0 = hc * 64;

    if (tid < 64) {
        float v = ba[h0 + tid];
        #pragma unroll
        for (int cc = 0; cc < KT; cc++)
            v += g_p_hid[((size_t)cc * Bn + b) * Hn + h0 + tid];
        s_hid[tid] = v;
        s_vw[tid]  = vw[h0 + tid];
    }

    const int a_row = lane & 15;
    const int a_col8 = (lane >> 4) * 8;
    const int g = lane >> 3;
    const int b_row = ((g >> 1) * 8) + (lane & 7);
    const int b_col8 = (g & 1) * 8;

    float acc[2][4][4];
    #pragma unroll
    for (int i = 0; i < 2; i++)
        #pragma unroll
        for (int j = 0; j < 4; j++)
            #pragma unroll
            for (int q = 0; q < 4; q++) acc[i][j][q] = 0.f;

    pf_energy(0, 0, sbase, b, h0, tid); CPA_COMMIT();
    pf_energy(1, 1, sbase, b, h0, tid); CPA_COMMIT();

    for (int c = 0; c < NCHE; c++) {
        CPA_WAIT1();
        __syncthreads();
        const int st = c % 3;
        const uint32_t ab = sbase + st * STAGE_E;
        #pragma unroll
        for (int s = 0; s < 2; s++) {
            uint32_t ah[2][4];
            #pragma unroll
            for (int i = 0; i < 2; i++) {
                uint32_t off = (uint32_t)((wm * 32 + i * 16 + a_row) * 80
                                          + (s * 16 + a_col8) * 2);
                ldmx4(ah[i], ab + off);
            }
            uint32_t bh2[2][4];
            #pragma unroll
            for (int j2 = 0; j2 < 2; j2++) {
                uint32_t off = (uint32_t)((wn * 32 + j2 * 16 + b_row) * 80
                                          + (s * 16 + b_col8) * 2);
                ldmx4(bh2[j2], ab + 10240 + off);
            }
            #pragma unroll
            for (int i = 0; i < 2; i++)
                #pragma unroll
                for (int j = 0; j < 4; j++)
                    mma16816(acc[i][j], ah[i], &bh2[j >> 1][(j & 1) * 2]);
        }
        pf_energy(c + 2, (c + 2) % 3, sbase, b, h0, tid);
        CPA_COMMIT();
    }

    #pragma unroll
    for (int i = 0; i < 2; i++) {
        float p1 = 0.f, p2 = 0.f;
        #pragma unroll
        for (int j = 0; j < 4; j++) {
            int hl = wn * 32 + j * 8 + tq * 2;
            float v0 = s_vw[hl], v1 = s_vw[hl + 1];
            float hp0 = s_hid[hl], hp1 = s_hid[hl + 1];
            p1 += v0 * tanhf(acc[i][j][0] + hp0) + v1 * tanhf(acc[i][j][1] + hp1);
            p2 += v0 * tanhf(acc[i][j][2] + hp0) + v1 * tanhf(acc[i][j][3] + hp1);
        }
        p1 += __shfl_xor_sync(0xffffffffu, p1, 1);
        p1 += __shfl_xor_sync(0xffffffffu, p1, 2);
        p2 += __shfl_xor_sync(0xffffffffu, p2, 1);
        p2 += __shfl_xor_sync(0xffffffffu, p2, 2);
        if (tq == 0) {
            int s1 = wm * 32 + i * 16 + gq;
            s_red[s1][wn] = p1;
            s_red[s1 + 8][wn] = p2;
        }
    }
    __syncthreads();
    if (tid < 128)
        g_scorep[(b * 8 + hc) * Sn + tid] = s_red[tid][0] + s_red[tid][1];
}

// ---------------- 3) fused emb + softmax + weighted + xin + xcat ----------------
__global__ __launch_bounds__(256)
void k_attn_ctx(const int* __restrict__ ids, const float* __restrict__ table,
                const int* __restrict__ mask, const float* __restrict__ enc,
                float* __restrict__ out_a) {
    const int b = blockIdx.x;
    const int tid = threadIdx.x;
    __shared__ float red[128];
    __shared__ float a_s[Sn];

    float v = 0.f;
    if (tid < 128) {
        #pragma unroll
        for (int c = 0; c < 8; c++) v += g_scorep[(b * 8 + c) * Sn + tid];
        if (mask[b * Sn + tid] == 0) v = NEGV;
        red[tid] = v;
    }
    __syncthreads();
    #pragma unroll
    for (int off = 64; off > 0; off >>= 1) {
        if (tid < off) red[tid] = fmaxf(red[tid], red[tid + off]);
        __syncthreads();
    }
    float m = red[0];
    __syncthreads();
    float e = 0.f;
    if (tid < 128) { e = expf(v - m); red[tid] = e; }
    __syncthreads();
    #pragma unroll
    for (int off = 64; off > 0; off >>= 1) {
        if (tid < off) red[tid] += red[tid + off];
        __syncthreads();
    }
    if (tid < 128) {
        float a = e / red[0];
        a_s[tid] = a;
        out_a[A_OFF + b * Sn + tid] = a;
    }
    __syncthreads();

    const int e0 = tid * 4;
    float4 acc = make_float4(0.f, 0.f, 0.f, 0.f);
    #pragma unroll 4
    for (int s = 0; s < Sn; s++) {
        float a = a_s[s];
        float4 ev = *(const float4*)(enc + ((size_t)(s * Bn + b)) * H2n + e0);
        acc.x += a * ev.x; acc.y += a * ev.y; acc.z += a * ev.z; acc.w += a * ev.w;
    }
    *(float4*)(g_xin + (size_t)b * XDIM + En + e0) = acc;
    int cb = b * CDIMP + Hn + e0;
    ((uint32_t*)g_xcat_h)[cb / 2]     = pack2h(acc.x, acc.y);
    ((uint32_t*)g_xcat_h)[cb / 2 + 1] = pack2h(acc.z, acc.w);

    const int id = ids[b];
    for (int idx = tid; idx < En; idx += 256) {
        float val = table[(size_t)id * En + idx];
        g_xin[(size_t)b * XDIM + idx] = val;
        g_xcat_h[b * CDIMP + Hn + H2n + idx] = __float2half_rn(val);
    }
    if (tid < CDIMP - CDIM)
        g_xcat_h[b * CDIMP + CDIM + tid] = __float2half_rn(0.f);
}

// ---------------- 4) gx partial GEMM ----------------
__global__ __launch_bounds__(256)
void k_gemm_gx(const float* __restrict__ Wih) {
    gemm_part_body(g_xin, XDIM, XDIM, Wih, XDIM, g_p_gx, H3n,
                   blockIdx.x * 64, blockIdx.y);
}

// ---------------- 5) gates + h_new + xcat(h_new) ----------------
__global__ void k_gru(const float* __restrict__ hidden,
                      const float* __restrict__ bih, const float* __restrict__ bhh,
                      float* __restrict__ out) {
    int idx = blockIdx.x * blockDim.x + threadIdx.x;
    if (idx >= Bn * Hn) return;
    int b = idx / Hn, c = idx - b * Hn;
    float gx0 = bih[c], gx1 = bih[Hn + c], gx2 = bih[2 * Hn + c];
    float gh0 = bhh[c], gh1 = bhh[Hn + c], gh2 = bhh[2 * Hn + c];
    #pragma unroll
    for (int cc = 0; cc < KT; cc++) {
        size_t base = ((size_t)cc * Bn + b) * H3n;
        gx0 += g_p_gx[base + c];
        gx1 += g_p_gx[base + Hn + c];
        gx2 += g_p_gx[base + 2 * Hn + c];
        gh0 += g_p_gh[base + c];
        gh1 += g_p_gh[base + Hn + c];
        gh2 += g_p_gh[base + 2 * Hn + c];
    }
    float r = 1.f / (1.f + expf(-(gx0 + gh0)));
    float z = 1.f / (1.f + expf(-(gx1 + gh1)));
    float n = tanhf(gx2 + r * gh2);
    float val = (1.f - z) * n + z * hidden[(size_t)b * Hn + c];
    out[HN_OFF + b * Hn + c] = val;
    g_xcat_h[b * CDIMP + c] = __float2half_rn(val);
}

// ---------------- 6) output GEMM: W_h x X_h, single MMA, 4-stage ----------------
#define NCHO 58
#define STAGE_O 21504      // W fp32 16384 | Xh 5120
#define SMEM_O  (4 * STAGE_O)

__device__ __forceinline__ void pf_out(int c, int st, uint32_t sbase,
                                       const float* Wout, int v0, int tid) {
    if (c >= NCHO) return;
    int k0 = c * 32;
    uint32_t wb = sbase + st * STAGE_O;
    #pragma unroll
    for (int it = 0; it < 4; it++) {
        int m = tid + it * 256;
        int row = m >> 3, kc = m & 7;
        int vr = v0 + row; if (vr >= Vn) vr = Vn - 1;
        int gk = k0 + kc * 4;
        int rem = CDIM - gk;
        int bytes = rem >= 4 ? 16 : (rem > 0 ? rem * 4 : 0);
        int gko = rem > 0 ? gk : 0;
        cpa_cg(wb + row * 128 + (((kc ^ (row & 7)) << 4)),
               Wout + (size_t)vr * CDIM + gko, bytes);
    }
    {
        int row = tid >> 2, ch = tid & 3;
        int gk = k0 + ch * 8;
        int rem = CDIMP - gk;
        int bytes = rem >= 8 ? 16 : (rem > 0 ? rem * 2 : 0);
        int gko = rem > 0 ? gk : 0;
        cpa_cg(wb + 16384 + row * 80 + ch * 16,
               g_xcat_h + (size_t)row * CDIMP + gko, bytes);
    }
}

__global__ __launch_bounds__(256, 2)
void k_out_mma(const float* __restrict__ Wout, const float* __restrict__ bout,
               float* __restrict__ pred) {
    extern __shared__ __align__(16) char dsm[];
    const uint32_t sbase = smem_u32(dsm);
    const int tid = threadIdx.x;
    const int lane = tid & 31, wid = tid >> 5;
    const int wm = wid >> 1, wn = wid & 1;
    const int gq = lane >> 2, tq = lane & 3;
    const int v0 = blockIdx.x * 128;
    const int g = lane >> 3;
    const int b_row = ((g >> 1) * 8) + (lane & 7);
    const int b_col8 = (g & 1) * 8;

    float acc[2][4][4];
    #pragma unroll
    for (int i = 0; i < 2; i++)
        #pragma unroll
        for (int j = 0; j < 4; j++)
            #pragma unroll
            for (int q = 0; q < 4; q++) acc[i][j][q] = 0.f;

    pf_out(0, 0, sbase, Wout, v0, tid); CPA_COMMIT();
    pf_out(1, 1, sbase, Wout, v0, tid); CPA_COMMIT();
    pf_out(2, 2, sbase, Wout, v0, tid); CPA_COMMIT();

    for (int c = 0; c < NCHO; c++) {
        CPA_WAIT2();
        __syncthreads();
        const int st = c & 3;
        const uint32_t wb = sbase + st * STAGE_O;
        #pragma unroll
        for (int s = 0; s < 2; s++) {
            const int kk = s * 16 + tq * 2;
            uint32_t ah[2][4];
            #pragma unroll
            for (int i = 0; i < 2; i++) {
                int r = wm * 32 + i * 16 + gq;
                float2 x0 = lds2(wb + swaddr(r, kk));
                float2 x1 = lds2(wb + swaddr(r + 8, kk));
                float2 x2 = lds2(wb + swaddr(r, kk + 8));
                float2 x3 = lds2(wb + swaddr(r + 8, kk + 8));
                ah[i][0] = pack2h(x0.x, x0.y);
                ah[i][1] = pack2h(x1.x, x1.y);
                ah[i][2] = pack2h(x2.x, x2.y);
                ah[i][3] = pack2h(x3.x, x3.y);
            }
            uint32_t bh2[2][4];
            #pragma unroll
            for (int j2 = 0; j2 < 2; j2++) {
                uint32_t off = (uint32_t)((wn * 32 + j2 * 16 + b_row) * 80
                                          + (s * 16 + b_col8) * 2);
                ldmx4(bh2[j2], wb + 16384 + off);
            }
            #pragma unroll
            for (int i = 0; i < 2; i++)
                #pragma unroll
                for (int j = 0; j < 4; j++)
                    mma16816(acc[i][j], ah[i], &bh2[j >> 1][(j & 1) * 2]);
        }
        pf_out(c + 3, (c + 3) & 3, sbase, Wout, v0, tid);
        CPA_COMMIT();
    }

    #pragma unroll
    for (int i = 0; i < 2; i++) {
        int v1 = v0 + wm * 32 + i * 16 + gq;
        int v2 = v1 + 8;
        float bo1 = (v1 < Vn) ? bout[v1] : 0.f;
        float bo2 = (v2 < Vn) ? bout[v2] : 0.f;
        #pragma unroll
        for (int j = 0; j < 4; j++) {
            int bb = wn * 32 + j * 8 + tq * 2;
            if (v1 < Vn) {
                pred[(size_t)bb * Vn + v1]       = acc[i][j][0] + bo1;
                pred[(size_t)(bb + 1) * Vn + v1] = acc[i][j][1] + bo1;
            }
            if (v2 < Vn) {
                pred[(size_t)bb * Vn + v2]       = acc[i][j][2] + bo2;
                pred[(size_t)(bb + 1) * Vn + v2] = acc[i][j][3] + bo2;
            }
        }
    }
}

// ---------------- launch ----------------
extern "C" void kernel_launch(void* const* d_in, const int* in_sizes, int n_in,
                              void* d_out, int out_size) {
    const int*   ids    = (const int*)  d_in[0];
    const float* hidden = (const float*)d_in[1];
    const float* enc    = (const float*)d_in[2];
    const int*   mask   = (const int*)  d_in[3];
    const float* table  = (const float*)d_in[4];
    const float* Wa     = (const float*)d_in[5];
    const float* ba     = (const float*)d_in[6];
    const float* vw     = (const float*)d_in[7];
    const float* Wih    = (const float*)d_in[8];
    const float* Whh    = (const float*)d_in[9];
    const float* bih    = (const float*)d_in[10];
    const float* bhh    = (const float*)d_in[11];
    const float* Wout   = (const float*)d_in[12];
    const float* bout   = (const float*)d_in[13];
    float* out = (float*)d_out;

    static int attr_done = 0;
    if (!attr_done) {
        cudaFuncSetAttribute(k_energy_mma, cudaFuncAttributeMaxDynamicSharedMemorySize, SMEM_E);
        cudaFuncSetAttribute(k_out_mma,    cudaFuncAttributeMaxDynamicSharedMemorySize, SMEM_O);
        attr_done = 1;
    }

    k_prep<<<NB_PREP, 256>>>(enc, Wa, hidden, Whh);
    k_energy_mma<<<dim3(8, Bn), 256, SMEM_E>>>(vw, ba);
    k_attn_ctx<<<Bn, 256>>>(ids, table, mask, enc, out);
    k_gemm_gx<<<dim3(24, KT), 256>>>(Wih);
    k_gru<<<(Bn * Hn + 255) / 256, 256>>>(hidden, bih, bhh, out);
    k_out_mma<<<(Vn + 127) / 128, 256, SMEM_O>>>(Wout, bout, out + PRED_OFF);
}